// round 5
// baseline (speedup 1.0000x reference)
#include <cuda_runtime.h>
#include <cuda_fp16.h>

typedef unsigned int u32;

#define B_ 4
#define H_ 16
#define S_ 2048
#define D_ 64
#define NKT 16
#define THREADS 256
#define KQ_STR 36      // u32 per K smem row; bank = 4g+i -> conflict-free frag loads
#define VT_STR 68      // u32 per Vt smem row; 68 mod 32 = 4 -> conflict-free frag loads
#define AB_STR 68      // floats per abuf row

__device__ u32   g_mbits[(size_t)B_ * S_ * (S_ / 32)];   // 2 MB mask bitfield
__device__ float g_inv[(size_t)B_ * H_ * S_];            // per-row 1/sum

// smem byte offsets
#define SM_KHI  0
#define SM_KLO  (SM_KHI  + 128 * KQ_STR * 4)             // 18432
#define SM_VTHI (SM_KLO  + 128 * KQ_STR * 4)
#define SM_VTLO (SM_VTHI + 64 * VT_STR * 4)              // 17408
#define SM_ABUF (SM_VTLO + 64 * VT_STR * 4)
#define SMEM_BYTES (SM_ABUF + 8 * 16 * AB_STR * 4)       // 106496 B -> 2 CTAs/SM

__device__ __forceinline__ void mma16816(float c[4], const u32 a[4], u32 b0, u32 b1) {
    asm volatile("mma.sync.aligned.m16n8k16.row.col.f32.f16.f16.f32 "
                 "{%0,%1,%2,%3}, {%4,%5,%6,%7}, {%8,%9}, {%0,%1,%2,%3};"
                 : "+f"(c[0]), "+f"(c[1]), "+f"(c[2]), "+f"(c[3])
                 : "r"(a[0]), "r"(a[1]), "r"(a[2]), "r"(a[3]), "r"(b0), "r"(b1));
}

__device__ __forceinline__ void split2(float x, float y, u32& h, u32& l) {
    __half hx = __float2half_rn(x), hy = __float2half_rn(y);
    __half lx = __float2half_rn(x - __half2float(hx));
    __half ly = __float2half_rn(y - __half2float(hy));
    __half2 H = __halves2half2(hx, hy), L = __halves2half2(lx, ly);
    h = *reinterpret_cast<u32*>(&H);
    l = *reinterpret_cast<u32*>(&L);
}

// stage 128x64 fp32 row-major K -> hi/lo fp16 smem [128][KQ_STR u32]
__device__ __forceinline__ void stage_k(const float* __restrict__ src,
                                        u32* hi, u32* lo, int tid) {
    const float4* s4 = (const float4*)src;
    #pragma unroll
    for (int it = 0; it < 8; ++it) {
        int idx = it * THREADS + tid;
        int r = idx >> 4, c4 = idx & 15;
        float4 v = s4[idx];
        u32 h0, l0, h1, l1;
        split2(v.x, v.y, h0, l0);
        split2(v.z, v.w, h1, l1);
        int o = r * KQ_STR + c4 * 2;
        *(uint2*)(hi + o) = make_uint2(h0, h1);
        *(uint2*)(lo + o) = make_uint2(l0, l1);
    }
}

// stage 128x64 fp32 V row-major -> transposed hi/lo fp16 smem Vt[64 d][VT_STR u32]
__device__ __forceinline__ void stage_vt(const float* __restrict__ src,
                                         u32* hi, u32* lo, int tid) {
    const float4* s4 = (const float4*)src;
    #pragma unroll
    for (int it = 0; it < 4; ++it) {
        int idx = it * THREADS + tid;
        int d4 = idx & 15, kp = idx >> 4;
        float4 a = s4[(2 * kp) * 16 + d4];
        float4 b = s4[(2 * kp + 1) * 16 + d4];
        float av[4] = {a.x, a.y, a.z, a.w};
        float bv[4] = {b.x, b.y, b.z, b.w};
        #pragma unroll
        for (int dd = 0; dd < 4; ++dd) {
            u32 h, l;
            split2(av[dd], bv[dd], h, l);
            hi[(4 * d4 + dd) * VT_STR + kp] = h;
            lo[(4 * d4 + dd) * VT_STR + kp] = l;
        }
    }
}

__global__ void maskbits_kernel(const int* __restrict__ mask) {
    int w = blockIdx.x * blockDim.x + threadIdx.x;
    const int4* src = (const int4*)mask + (size_t)w * 8;
    u32 bits = 0;
    #pragma unroll
    for (int i = 0; i < 8; ++i) {
        int4 v = src[i];
        bits |= (v.x != 0 ? 1u : 0u) << (i * 4);
        bits |= (v.y != 0 ? 1u : 0u) << (i * 4 + 1);
        bits |= (v.z != 0 ? 1u : 0u) << (i * 4 + 2);
        bits |= (v.w != 0 ? 1u : 0u) << (i * 4 + 3);
    }
    g_mbits[w] = bits;
}

// attn[i] *= g_inv[row]; 512 float4 per row
__global__ void norm_kernel(float* __restrict__ attn) {
    size_t t = (size_t)blockIdx.x * blockDim.x + threadIdx.x;
    float inv = __ldg(&g_inv[t >> 9]);
    float4* a4 = (float4*)attn;
    float4 v = a4[t];
    v.x *= inv; v.y *= inv; v.z *= inv; v.w *= inv;
    a4[t] = v;
}

__global__ __launch_bounds__(THREADS, 2)
void attn_mma(const float* __restrict__ Q, const float* __restrict__ K,
              const float* __restrict__ V, float* __restrict__ outp,
              float* __restrict__ attn)
{
    extern __shared__ char sm[];
    u32* KHI  = (u32*)(sm + SM_KHI);
    u32* KLO  = (u32*)(sm + SM_KLO);
    u32* VTHI = (u32*)(sm + SM_VTHI);
    u32* VTLO = (u32*)(sm + SM_VTLO);

    const int tid = threadIdx.x, wid = tid >> 5, lane = tid & 31;
    const int g = lane >> 2, i = lane & 3;
    const int bh = blockIdx.x, b = bh >> 4, q0 = blockIdx.y * 128;
    const int qw = wid * 16;

    float* abuf = (float*)(sm + SM_ABUF) + wid * 16 * AB_STR;

    const float* Kb = K + (size_t)bh * S_ * D_;
    const float* Vb = V + (size_t)bh * S_ * D_;

    // ---- Q fragments straight from gmem (rows qw+g, qw+g+8), scale folded ----
    u32 qh[4][4], ql[4][4];
    {
        const float* qa = Q + ((size_t)bh * S_ + q0 + qw + g) * D_;
        const float* qb = qa + 8 * D_;
        #pragma unroll
        for (int kc = 0; kc < 4; ++kc) {
            float2 a0 = *(const float2*)(qa + 16 * kc + 2 * i);
            float2 a1 = *(const float2*)(qa + 16 * kc + 8 + 2 * i);
            float2 b0 = *(const float2*)(qb + 16 * kc + 2 * i);
            float2 b1 = *(const float2*)(qb + 16 * kc + 8 + 2 * i);
            split2(a0.x * 0.125f, a0.y * 0.125f, qh[kc][0], ql[kc][0]);
            split2(b0.x * 0.125f, b0.y * 0.125f, qh[kc][1], ql[kc][1]);
            split2(a1.x * 0.125f, a1.y * 0.125f, qh[kc][2], ql[kc][2]);
            split2(b1.x * 0.125f, b1.y * 0.125f, qh[kc][3], ql[kc][3]);
        }
    }

    const u32* mra = g_mbits + (size_t)(b * S_ + q0 + qw + g) * (S_ / 32);
    const u32* mrb = mra + 8 * (S_ / 32);

    float sa = 0.f, sb = 0.f;
    float o[8][4];
    #pragma unroll
    for (int d = 0; d < 8; ++d) o[d][0] = o[d][1] = o[d][2] = o[d][3] = 0.f;

    // =================== single pass: QK -> e -> attn(e) + e@V ===================
    for (int kt = 0; kt < NKT; ++kt) {
        __syncthreads();
        stage_k(Kb + (size_t)kt * 128 * D_, KHI, KLO, tid);
        stage_vt(Vb + (size_t)kt * 128 * D_, VTHI, VTLO, tid);
        __syncthreads();

        #pragma unroll
        for (int sub = 0; sub < 2; ++sub) {
            float c[8][4];
            #pragma unroll
            for (int j = 0; j < 8; ++j)
                c[j][0] = c[j][1] = c[j][2] = c[j][3] = 0.f;

            #pragma unroll
            for (int j = 0; j < 8; ++j) {
                int kbase = (sub * 64 + j * 8 + g) * KQ_STR + i;
                #pragma unroll
                for (int kc = 0; kc < 4; ++kc) {
                    u32 bh0 = KHI[kbase + kc * 8], bh1 = KHI[kbase + kc * 8 + 4];
                    u32 bl0 = KLO[kbase + kc * 8], bl1 = KLO[kbase + kc * 8 + 4];
                    mma16816(c[j], qh[kc], bh0, bh1);
                    mma16816(c[j], qh[kc], bl0, bl1);
                    mma16816(c[j], ql[kc], bh0, bh1);
                }
            }

            u32 ma0 = mra[kt * 4 + sub * 2], ma1 = mra[kt * 4 + sub * 2 + 1];
            u32 mb0 = mrb[kt * 4 + sub * 2], mb1 = mrb[kt * 4 + sub * 2 + 1];
            #pragma unroll
            for (int j = 0; j < 8; ++j) {
                int sh = 8 * (j & 3) + 2 * i;
                u32 wa = ((j < 4) ? ma0 : ma1) >> sh;
                u32 wb = ((j < 4) ? mb0 : mb1) >> sh;
                float e0 = (wa & 1u) ? __expf(c[j][0]) : 0.f;
                float e1 = (wa & 2u) ? __expf(c[j][1]) : 0.f;
                float e2 = (wb & 1u) ? __expf(c[j][2]) : 0.f;
                float e3 = (wb & 2u) ? __expf(c[j][3]) : 0.f;
                sa += e0 + e1;
                sb += e2 + e3;
                c[j][0] = e0; c[j][1] = e1; c[j][2] = e2; c[j][3] = e3;
            }

            // coalesced unnormalized-attn write via warp-private smem transpose
            if (attn) {
                #pragma unroll
                for (int j = 0; j < 8; ++j) {
                    *(float2*)&abuf[g * AB_STR + 8 * j + 2 * i]       = make_float2(c[j][0], c[j][1]);
                    *(float2*)&abuf[(g + 8) * AB_STR + 8 * j + 2 * i] = make_float2(c[j][2], c[j][3]);
                }
                __syncwarp();
                const int r2 = lane >> 4, c4 = lane & 15;
                #pragma unroll
                for (int rr = 0; rr < 8; ++rr) {
                    int row = rr * 2 + r2;
                    float4 v = *(float4*)&abuf[row * AB_STR + c4 * 4];
                    *(float4*)&attn[((size_t)bh * S_ + q0 + qw + row) * S_
                                    + (size_t)kt * 128 + sub * 64 + c4 * 4] = v;
                }
                __syncwarp();
            }

            // pack e fragments (hi/lo) from registers, accumulate e @ V
            u32 ah[4][4], al[4][4];
            #pragma unroll
            for (int kc = 0; kc < 4; ++kc) {
                split2(c[2 * kc][0],     c[2 * kc][1],     ah[kc][0], al[kc][0]);
                split2(c[2 * kc][2],     c[2 * kc][3],     ah[kc][1], al[kc][1]);
                split2(c[2 * kc + 1][0], c[2 * kc + 1][1], ah[kc][2], al[kc][2]);
                split2(c[2 * kc + 1][2], c[2 * kc + 1][3], ah[kc][3], al[kc][3]);
            }
            #pragma unroll
            for (int dblk = 0; dblk < 8; ++dblk) {
                int vb = (dblk * 8 + g) * VT_STR + sub * 32 + i;
                #pragma unroll
                for (int kc = 0; kc < 4; ++kc) {
                    u32 vh0 = VTHI[vb + kc * 8], vh1 = VTHI[vb + kc * 8 + 4];
                    u32 vl0 = VTLO[vb + kc * 8], vl1 = VTLO[vb + kc * 8 + 4];
                    mma16816(o[dblk], ah[kc], vh0, vh1);
                    mma16816(o[dblk], al[kc], vh0, vh1);
                    mma16816(o[dblk], ah[kc], vl0, vl1);
                }
            }
        }
    }

    // =================== epilogue: inv, scale out, write ===================
    sa += __shfl_xor_sync(0xffffffffu, sa, 1);
    sa += __shfl_xor_sync(0xffffffffu, sa, 2);
    sb += __shfl_xor_sync(0xffffffffu, sb, 1);
    sb += __shfl_xor_sync(0xffffffffu, sb, 2);
    const float inva = (sa > 0.f) ? (1.0f / sa) : 0.f;
    const float invb = (sb > 0.f) ? (1.0f / sb) : 0.f;

    if (i == 0) {
        g_inv[(size_t)bh * S_ + q0 + qw + g]     = inva;
        g_inv[(size_t)bh * S_ + q0 + qw + g + 8] = invb;
    }

    if (outp) {
        #pragma unroll
        for (int dblk = 0; dblk < 8; ++dblk) {
            *(float2*)&abuf[g * AB_STR + 8 * dblk + 2 * i] =
                make_float2(o[dblk][0] * inva, o[dblk][1] * inva);
            *(float2*)&abuf[(g + 8) * AB_STR + 8 * dblk + 2 * i] =
                make_float2(o[dblk][2] * invb, o[dblk][3] * invb);
        }
        __syncwarp();
        const int r2 = lane >> 4, c4 = lane & 15;
        #pragma unroll
        for (int rr = 0; rr < 8; ++rr) {
            int row = rr * 2 + r2;
            float4 v = *(float4*)&abuf[row * AB_STR + c4 * 4];
            *(float4*)&outp[((size_t)bh * S_ + q0 + qw + row) * D_ + c4 * 4] = v;
        }
    }
}

extern "C" void kernel_launch(void* const* d_in, const int* in_sizes, int n_in,
                              void* d_out, int out_size)
{
    const float* Q    = (const float*)d_in[0];
    const float* K    = (const float*)d_in[1];
    const float* V    = (const float*)d_in[2];
    const int*   mask = (const int*)d_in[3];

    const size_t OUT_E  = (size_t)B_ * H_ * S_ * D_;
    const size_t ATTN_E = (size_t)B_ * H_ * S_ * S_;
    float* o = nullptr; float* a = nullptr;
    if ((size_t)out_size >= OUT_E + ATTN_E) { o = (float*)d_out; a = (float*)d_out + OUT_E; }
    else if ((size_t)out_size == ATTN_E)    { a = (float*)d_out; }
    else                                    { o = (float*)d_out; }

    maskbits_kernel<<<(B_ * S_ * (S_ / 32)) / 256, 256>>>(mask);

    cudaFuncSetAttribute(attn_mma, cudaFuncAttributeMaxDynamicSharedMemorySize, SMEM_BYTES);
    dim3 grid(B_ * H_, S_ / 128);
    attn_mma<<<grid, THREADS, SMEM_BYTES>>>(Q, K, V, o, a);

    if (a) {
        size_t n4 = ATTN_E / 4;                       // 67108864 float4
        norm_kernel<<<(unsigned)(n4 / 256), 256>>>(a);
    }
}

// round 6
// speedup vs baseline: 1.4008x; 1.4008x over previous
#include <cuda_runtime.h>
#include <cuda_fp16.h>

typedef unsigned int u32;

#define B_ 4
#define H_ 16
#define S_ 2048
#define D_ 64
#define NKT 16
#define THREADS 256
#define KQ_STR 36      // u32 per K smem row (144B stride; mod128=16 -> ldmatrix conflict-free)
#define VT_STR 68      // u32 per Vt smem row (272B stride; mod128=16 -> conflict-free)
#define AB_STR 68      // floats per abuf row

__device__ u32   g_mbits[(size_t)B_ * S_ * (S_ / 32)];   // 2 MB mask bitfield
__device__ float g_inv[(size_t)B_ * H_ * S_];            // per-row 1/sum

// smem byte offsets
#define SM_KHI  0
#define SM_KLO  (SM_KHI  + 128 * KQ_STR * 4)
#define SM_VTHI (SM_KLO  + 128 * KQ_STR * 4)
#define SM_VTLO (SM_VTHI + 64 * VT_STR * 4)
#define SM_ABUF (SM_VTLO + 64 * VT_STR * 4)
#define SMEM_BYTES (SM_ABUF + 8 * 16 * AB_STR * 4)       // 106496 B

__device__ __forceinline__ void mma16816(float c[4], const u32 a[4], u32 b0, u32 b1) {
    asm volatile("mma.sync.aligned.m16n8k16.row.col.f32.f16.f16.f32 "
                 "{%0,%1,%2,%3}, {%4,%5,%6,%7}, {%8,%9}, {%0,%1,%2,%3};"
                 : "+f"(c[0]), "+f"(c[1]), "+f"(c[2]), "+f"(c[3])
                 : "r"(a[0]), "r"(a[1]), "r"(a[2]), "r"(a[3]), "r"(b0), "r"(b1));
}

__device__ __forceinline__ void ldm4(u32* r, u32 addr) {
    asm volatile("ldmatrix.sync.aligned.m8n8.x4.shared.b16 {%0,%1,%2,%3}, [%4];"
                 : "=r"(r[0]), "=r"(r[1]), "=r"(r[2]), "=r"(r[3]) : "r"(addr));
}

__device__ __forceinline__ u32 smem_u32(const void* p) {
    return (u32)__cvta_generic_to_shared(p);
}

__device__ __forceinline__ void split2(float x, float y, u32& h, u32& l) {
    __half hx = __float2half_rn(x), hy = __float2half_rn(y);
    __half lx = __float2half_rn(x - __half2float(hx));
    __half ly = __float2half_rn(y - __half2float(hy));
    __half2 H = __halves2half2(hx, hy), L = __halves2half2(lx, ly);
    h = *reinterpret_cast<u32*>(&H);
    l = *reinterpret_cast<u32*>(&L);
}

// stage 128x64 fp32 row-major K -> hi/lo fp16 smem [128][KQ_STR u32]
__device__ __forceinline__ void stage_k(const float* __restrict__ src,
                                        u32* hi, u32* lo, int tid) {
    const float4* s4 = (const float4*)src;
    #pragma unroll
    for (int it = 0; it < 8; ++it) {
        int idx = it * THREADS + tid;
        int r = idx >> 4, c4 = idx & 15;
        float4 v = s4[idx];
        u32 h0, l0, h1, l1;
        split2(v.x, v.y, h0, l0);
        split2(v.z, v.w, h1, l1);
        int o = r * KQ_STR + c4 * 2;
        *(uint2*)(hi + o) = make_uint2(h0, h1);
        *(uint2*)(lo + o) = make_uint2(l0, l1);
    }
}

// stage 128x64 fp32 V row-major -> transposed hi/lo fp16 smem Vt[64 d][VT_STR u32]
__device__ __forceinline__ void stage_vt(const float* __restrict__ src,
                                         u32* hi, u32* lo, int tid) {
    const float4* s4 = (const float4*)src;
    #pragma unroll
    for (int it = 0; it < 4; ++it) {
        int idx = it * THREADS + tid;
        int d4 = idx & 15, kp = idx >> 4;
        float4 a = s4[(2 * kp) * 16 + d4];
        float4 b = s4[(2 * kp + 1) * 16 + d4];
        float av[4] = {a.x, a.y, a.z, a.w};
        float bv[4] = {b.x, b.y, b.z, b.w};
        #pragma unroll
        for (int dd = 0; dd < 4; ++dd) {
            u32 h, l;
            split2(av[dd], bv[dd], h, l);
            hi[(4 * d4 + dd) * VT_STR + kp] = h;
            lo[(4 * d4 + dd) * VT_STR + kp] = l;
        }
    }
}

__global__ void maskbits_kernel(const int* __restrict__ mask) {
    int w = blockIdx.x * blockDim.x + threadIdx.x;
    const int4* src = (const int4*)mask + (size_t)w * 8;
    u32 bits = 0;
    #pragma unroll
    for (int i = 0; i < 8; ++i) {
        int4 v = src[i];
        bits |= (v.x != 0 ? 1u : 0u) << (i * 4);
        bits |= (v.y != 0 ? 1u : 0u) << (i * 4 + 1);
        bits |= (v.z != 0 ? 1u : 0u) << (i * 4 + 2);
        bits |= (v.w != 0 ? 1u : 0u) << (i * 4 + 3);
    }
    g_mbits[w] = bits;
}

// attn[i] *= g_inv[row]; one float4 per thread
__global__ void norm_kernel(float* __restrict__ attn) {
    size_t t = (size_t)blockIdx.x * blockDim.x + threadIdx.x;
    float inv = __ldg(&g_inv[t >> 9]);
    float4* a4 = (float4*)attn;
    float4 v = a4[t];
    v.x *= inv; v.y *= inv; v.z *= inv; v.w *= inv;
    a4[t] = v;
}

__global__ __launch_bounds__(THREADS, 1)
void attn_mma(const float* __restrict__ Q, const float* __restrict__ K,
              const float* __restrict__ V, float* __restrict__ outp,
              float* __restrict__ attn)
{
    extern __shared__ char sm[];
    u32* KHI  = (u32*)(sm + SM_KHI);
    u32* KLO  = (u32*)(sm + SM_KLO);
    u32* VTHI = (u32*)(sm + SM_VTHI);
    u32* VTLO = (u32*)(sm + SM_VTLO);

    const u32 khi_u  = smem_u32(KHI),  klo_u  = smem_u32(KLO);
    const u32 vthi_u = smem_u32(VTHI), vtlo_u = smem_u32(VTLO);

    const int tid = threadIdx.x, wid = tid >> 5, lane = tid & 31;
    const int g = lane >> 2, i = lane & 3;
    const int trow = lane & 7, tmat = lane >> 3;     // ldmatrix addressing
    const int bh = blockIdx.x, b = bh >> 4, q0 = blockIdx.y * 128;
    const int qw = wid * 16;

    float* abuf = (float*)(sm + SM_ABUF) + wid * 16 * AB_STR;

    const float* Kb = K + (size_t)bh * S_ * D_;
    const float* Vb = V + (size_t)bh * S_ * D_;

    // ---- Q fragments straight from gmem (rows qw+g, qw+g+8), scale folded ----
    u32 qh[4][4], ql[4][4];
    {
        const float* qa = Q + ((size_t)bh * S_ + q0 + qw + g) * D_;
        const float* qb = qa + 8 * D_;
        #pragma unroll
        for (int kc = 0; kc < 4; ++kc) {
            float2 a0 = *(const float2*)(qa + 16 * kc + 2 * i);
            float2 a1 = *(const float2*)(qa + 16 * kc + 8 + 2 * i);
            float2 b0 = *(const float2*)(qb + 16 * kc + 2 * i);
            float2 b1 = *(const float2*)(qb + 16 * kc + 8 + 2 * i);
            split2(a0.x * 0.125f, a0.y * 0.125f, qh[kc][0], ql[kc][0]);
            split2(b0.x * 0.125f, b0.y * 0.125f, qh[kc][1], ql[kc][1]);
            split2(a1.x * 0.125f, a1.y * 0.125f, qh[kc][2], ql[kc][2]);
            split2(b1.x * 0.125f, b1.y * 0.125f, qh[kc][3], ql[kc][3]);
        }
    }

    const u32* mra = g_mbits + (size_t)(b * S_ + q0 + qw + g) * (S_ / 32);
    const u32* mrb = mra + 8 * (S_ / 32);

    float sa = 0.f, sb = 0.f;
    float o[8][4];
    #pragma unroll
    for (int d = 0; d < 8; ++d) o[d][0] = o[d][1] = o[d][2] = o[d][3] = 0.f;

    // =================== single pass: QK -> e -> attn(e) + e@V ===================
    for (int kt = 0; kt < NKT; ++kt) {
        __syncthreads();
        stage_k(Kb + (size_t)kt * 128 * D_, KHI, KLO, tid);
        stage_vt(Vb + (size_t)kt * 128 * D_, VTHI, VTLO, tid);
        __syncthreads();

        #pragma unroll
        for (int sub = 0; sub < 2; ++sub) {
            float c[8][4];
            #pragma unroll
            for (int j = 0; j < 8; ++j)
                c[j][0] = c[j][1] = c[j][2] = c[j][3] = 0.f;

            #pragma unroll
            for (int j = 0; j < 8; ++j) {
                // B fragments for this n-octet via ldmatrix.x4 (regs [2kc],[2kc+1] = b0,b1 of chunk kc)
                u32 rb = (u32)(((sub * 64 + j * 8 + trow) * KQ_STR + tmat * 4) * 4);
                u32 bhv[8], blv[8];
                ldm4(&bhv[0], khi_u + rb);
                ldm4(&bhv[4], khi_u + rb + 64);
                ldm4(&blv[0], klo_u + rb);
                ldm4(&blv[4], klo_u + rb + 64);
                #pragma unroll
                for (int kc = 0; kc < 4; ++kc) {
                    mma16816(c[j], qh[kc], bhv[2 * kc], bhv[2 * kc + 1]);
                    mma16816(c[j], qh[kc], blv[2 * kc], blv[2 * kc + 1]);
                    mma16816(c[j], ql[kc], bhv[2 * kc], bhv[2 * kc + 1]);
                }
            }

            u32 ma0 = mra[kt * 4 + sub * 2], ma1 = mra[kt * 4 + sub * 2 + 1];
            u32 mb0 = mrb[kt * 4 + sub * 2], mb1 = mrb[kt * 4 + sub * 2 + 1];
            #pragma unroll
            for (int j = 0; j < 8; ++j) {
                int sh = 8 * (j & 3) + 2 * i;
                u32 wa = ((j < 4) ? ma0 : ma1) >> sh;
                u32 wb = ((j < 4) ? mb0 : mb1) >> sh;
                float e0 = (wa & 1u) ? __expf(c[j][0]) : 0.f;
                float e1 = (wa & 2u) ? __expf(c[j][1]) : 0.f;
                float e2 = (wb & 1u) ? __expf(c[j][2]) : 0.f;
                float e3 = (wb & 2u) ? __expf(c[j][3]) : 0.f;
                sa += e0 + e1;
                sb += e2 + e3;
                c[j][0] = e0; c[j][1] = e1; c[j][2] = e2; c[j][3] = e3;
            }

            // coalesced unnormalized-attn write via warp-private smem transpose
            if (attn) {
                #pragma unroll
                for (int j = 0; j < 8; ++j) {
                    *(float2*)&abuf[g * AB_STR + 8 * j + 2 * i]       = make_float2(c[j][0], c[j][1]);
                    *(float2*)&abuf[(g + 8) * AB_STR + 8 * j + 2 * i] = make_float2(c[j][2], c[j][3]);
                }
                __syncwarp();
                const int r2 = lane >> 4, c4 = lane & 15;
                #pragma unroll
                for (int rr = 0; rr < 8; ++rr) {
                    int row = rr * 2 + r2;
                    float4 v = *(float4*)&abuf[row * AB_STR + c4 * 4];
                    *(float4*)&attn[((size_t)bh * S_ + q0 + qw + row) * S_
                                    + (size_t)kt * 128 + sub * 64 + c4 * 4] = v;
                }
                __syncwarp();
            }

            // pack e fragments (hi/lo) from registers, accumulate e @ V
            u32 ah[4][4], al[4][4];
            #pragma unroll
            for (int kc = 0; kc < 4; ++kc) {
                split2(c[2 * kc][0],     c[2 * kc][1],     ah[kc][0], al[kc][0]);
                split2(c[2 * kc][2],     c[2 * kc][3],     ah[kc][1], al[kc][1]);
                split2(c[2 * kc + 1][0], c[2 * kc + 1][1], ah[kc][2], al[kc][2]);
                split2(c[2 * kc + 1][2], c[2 * kc + 1][3], ah[kc][3], al[kc][3]);
            }
            #pragma unroll
            for (int dblk = 0; dblk < 8; ++dblk) {
                u32 rb = (u32)(((dblk * 8 + trow) * VT_STR + sub * 32 + tmat * 4) * 4);
                u32 vh[8], vl[8];
                ldm4(&vh[0], vthi_u + rb);
                ldm4(&vh[4], vthi_u + rb + 64);
                ldm4(&vl[0], vtlo_u + rb);
                ldm4(&vl[4], vtlo_u + rb + 64);
                #pragma unroll
                for (int kc = 0; kc < 4; ++kc) {
                    mma16816(o[dblk], ah[kc], vh[2 * kc], vh[2 * kc + 1]);
                    mma16816(o[dblk], al[kc], vh[2 * kc], vh[2 * kc + 1]);
                    mma16816(o[dblk], ah[kc], vl[2 * kc], vl[2 * kc + 1]);
                }
            }
        }
    }

    // =================== epilogue: inv, scale out, write ===================
    sa += __shfl_xor_sync(0xffffffffu, sa, 1);
    sa += __shfl_xor_sync(0xffffffffu, sa, 2);
    sb += __shfl_xor_sync(0xffffffffu, sb, 1);
    sb += __shfl_xor_sync(0xffffffffu, sb, 2);
    const float inva = (sa > 0.f) ? (1.0f / sa) : 0.f;
    const float invb = (sb > 0.f) ? (1.0f / sb) : 0.f;

    if (i == 0) {
        g_inv[(size_t)bh * S_ + q0 + qw + g]     = inva;
        g_inv[(size_t)bh * S_ + q0 + qw + g + 8] = invb;
    }

    if (outp) {
        #pragma unroll
        for (int dblk = 0; dblk < 8; ++dblk) {
            *(float2*)&abuf[g * AB_STR + 8 * dblk + 2 * i] =
                make_float2(o[dblk][0] * inva, o[dblk][1] * inva);
            *(float2*)&abuf[(g + 8) * AB_STR + 8 * dblk + 2 * i] =
                make_float2(o[dblk][2] * invb, o[dblk][3] * invb);
        }
        __syncwarp();
        const int r2 = lane >> 4, c4 = lane & 15;
        #pragma unroll
        for (int rr = 0; rr < 8; ++rr) {
            int row = rr * 2 + r2;
            float4 v = *(float4*)&abuf[row * AB_STR + c4 * 4];
            *(float4*)&outp[((size_t)bh * S_ + q0 + qw + row) * D_ + c4 * 4] = v;
        }
    }
}

extern "C" void kernel_launch(void* const* d_in, const int* in_sizes, int n_in,
                              void* d_out, int out_size)
{
    const float* Q    = (const float*)d_in[0];
    const float* K    = (const float*)d_in[1];
    const float* V    = (const float*)d_in[2];
    const int*   mask = (const int*)d_in[3];

    const size_t OUT_E  = (size_t)B_ * H_ * S_ * D_;
    const size_t ATTN_E = (size_t)B_ * H_ * S_ * S_;
    float* o = nullptr; float* a = nullptr;
    if ((size_t)out_size >= OUT_E + ATTN_E) { o = (float*)d_out; a = (float*)d_out + OUT_E; }
    else if ((size_t)out_size == ATTN_E)    { a = (float*)d_out; }
    else                                    { o = (float*)d_out; }

    maskbits_kernel<<<(B_ * S_ * (S_ / 32)) / 256, 256>>>(mask);

    cudaFuncSetAttribute(attn_mma, cudaFuncAttributeMaxDynamicSharedMemorySize, SMEM_BYTES);
    dim3 grid(B_ * H_, S_ / 128);
    attn_mma<<<grid, THREADS, SMEM_BYTES>>>(Q, K, V, o, a);

    if (a) {
        size_t n4 = ATTN_E / 4;
        norm_kernel<<<(unsigned)(n4 / 256), 256>>>(a);
    }
}

// round 7
// speedup vs baseline: 1.5497x; 1.1063x over previous
#include <cuda_runtime.h>
#include <cuda_fp16.h>

typedef unsigned int u32;

#define B_ 4
#define H_ 16
#define S_ 2048
#define D_ 64
#define NKT 16
#define THREADS 256
#define KQ_STR 36      // u32 per K smem row (144B stride; 4r-banks -> ldmatrix conflict-free)
#define VT_STR 68      // u32 per Vt smem row (272B stride; conflict-free ldmatrix)

__device__ u32   g_mbits[(size_t)B_ * S_ * (S_ / 32)];   // 2 MB mask bitfield
__device__ float g_inv[(size_t)B_ * H_ * S_];            // per-row 1/sum

// smem byte offsets
#define SM_KHI  0
#define SM_KLO  (SM_KHI  + 128 * KQ_STR * 4)
#define SM_VTHI (SM_KLO  + 128 * KQ_STR * 4)
#define SM_VTLO (SM_VTHI + 64 * VT_STR * 4)
#define SMEM_BYTES (SM_VTLO + 64 * VT_STR * 4)           // 71680 B -> 2 CTAs/SM

__device__ __forceinline__ void mma16816(float c[4], const u32 a[4], u32 b0, u32 b1) {
    asm volatile("mma.sync.aligned.m16n8k16.row.col.f32.f16.f16.f32 "
                 "{%0,%1,%2,%3}, {%4,%5,%6,%7}, {%8,%9}, {%0,%1,%2,%3};"
                 : "+f"(c[0]), "+f"(c[1]), "+f"(c[2]), "+f"(c[3])
                 : "r"(a[0]), "r"(a[1]), "r"(a[2]), "r"(a[3]), "r"(b0), "r"(b1));
}

__device__ __forceinline__ void ldm4(u32* r, u32 addr) {
    asm volatile("ldmatrix.sync.aligned.m8n8.x4.shared.b16 {%0,%1,%2,%3}, [%4];"
                 : "=r"(r[0]), "=r"(r[1]), "=r"(r[2]), "=r"(r[3]) : "r"(addr));
}

__device__ __forceinline__ u32 smem_u32(const void* p) {
    return (u32)__cvta_generic_to_shared(p);
}

__device__ __forceinline__ void split2(float x, float y, u32& h, u32& l) {
    __half hx = __float2half_rn(x), hy = __float2half_rn(y);
    __half lx = __float2half_rn(x - __half2float(hx));
    __half ly = __float2half_rn(y - __half2float(hy));
    __half2 H = __halves2half2(hx, hy), L = __halves2half2(lx, ly);
    h = *reinterpret_cast<u32*>(&H);
    l = *reinterpret_cast<u32*>(&L);
}

// stage 128x64 fp32 row-major K -> hi/lo fp16 smem [128][KQ_STR u32]
__device__ __forceinline__ void stage_k(const float* __restrict__ src,
                                        u32* hi, u32* lo, int tid) {
    const float4* s4 = (const float4*)src;
    #pragma unroll
    for (int it = 0; it < 8; ++it) {
        int idx = it * THREADS + tid;
        int r = idx >> 4, c4 = idx & 15;
        float4 v = s4[idx];
        u32 h0, l0, h1, l1;
        split2(v.x, v.y, h0, l0);
        split2(v.z, v.w, h1, l1);
        int o = r * KQ_STR + c4 * 2;
        *(uint2*)(hi + o) = make_uint2(h0, h1);
        *(uint2*)(lo + o) = make_uint2(l0, l1);
    }
}

// stage 128x64 fp32 V row-major -> transposed hi/lo fp16 smem Vt[64 d][VT_STR u32]
__device__ __forceinline__ void stage_vt(const float* __restrict__ src,
                                         u32* hi, u32* lo, int tid) {
    const float4* s4 = (const float4*)src;
    #pragma unroll
    for (int it = 0; it < 4; ++it) {
        int idx = it * THREADS + tid;
        int d4 = idx & 15, kp = idx >> 4;
        float4 a = s4[(2 * kp) * 16 + d4];
        float4 b = s4[(2 * kp + 1) * 16 + d4];
        float av[4] = {a.x, a.y, a.z, a.w};
        float bv[4] = {b.x, b.y, b.z, b.w};
        #pragma unroll
        for (int dd0 = 0; dd0 < 4; ++dd0) {
            int dd = (dd0 + d4) & 3;               // rotate -> fewer store conflicts
            u32 h, l;
            split2(av[dd], bv[dd], h, l);
            hi[(4 * d4 + dd) * VT_STR + kp] = h;
            lo[(4 * d4 + dd) * VT_STR + kp] = l;
        }
    }
}

__global__ void maskbits_kernel(const int* __restrict__ mask) {
    int w = blockIdx.x * blockDim.x + threadIdx.x;
    const int4* src = (const int4*)mask + (size_t)w * 8;
    u32 bits = 0;
    #pragma unroll
    for (int i = 0; i < 8; ++i) {
        int4 v = src[i];
        bits |= (v.x != 0 ? 1u : 0u) << (i * 4);
        bits |= (v.y != 0 ? 1u : 0u) << (i * 4 + 1);
        bits |= (v.z != 0 ? 1u : 0u) << (i * 4 + 2);
        bits |= (v.w != 0 ? 1u : 0u) << (i * 4 + 3);
    }
    g_mbits[w] = bits;
}

// attn[i] *= g_inv[row]; one float4 per thread
__global__ void norm_kernel(float* __restrict__ attn) {
    size_t t = (size_t)blockIdx.x * blockDim.x + threadIdx.x;
    float inv = __ldg(&g_inv[t >> 9]);
    float4* a4 = (float4*)attn;
    float4 v = a4[t];
    v.x *= inv; v.y *= inv; v.z *= inv; v.w *= inv;
    a4[t] = v;
}

__global__ __launch_bounds__(THREADS, 2)
void attn_mma(const float* __restrict__ Q, const float* __restrict__ K,
              const float* __restrict__ V, float* __restrict__ outp,
              float* __restrict__ attn)
{
    extern __shared__ char sm[];
    u32* KHI  = (u32*)(sm + SM_KHI);
    u32* KLO  = (u32*)(sm + SM_KLO);
    u32* VTHI = (u32*)(sm + SM_VTHI);
    u32* VTLO = (u32*)(sm + SM_VTLO);

    const u32 khi_u  = smem_u32(KHI),  klo_u  = smem_u32(KLO);
    const u32 vthi_u = smem_u32(VTHI), vtlo_u = smem_u32(VTLO);

    const int tid = threadIdx.x, wid = tid >> 5, lane = tid & 31;
    const int g = lane >> 2, i = lane & 3;
    const int trow = lane & 7, tmat = lane >> 3;
    const int bh = blockIdx.x, b = bh >> 4, q0 = blockIdx.y * 128;
    const int qw = wid * 16;

    const float* Kb = K + (size_t)bh * S_ * D_;
    const float* Vb = V + (size_t)bh * S_ * D_;

    // ---- Q fragments straight from gmem (rows qw+g, qw+g+8), scale folded ----
    u32 qh[4][4], ql[4][4];
    {
        const float* qa = Q + ((size_t)bh * S_ + q0 + qw + g) * D_;
        const float* qb = qa + 8 * D_;
        #pragma unroll
        for (int kc = 0; kc < 4; ++kc) {
            float2 a0 = *(const float2*)(qa + 16 * kc + 2 * i);
            float2 a1 = *(const float2*)(qa + 16 * kc + 8 + 2 * i);
            float2 b0 = *(const float2*)(qb + 16 * kc + 2 * i);
            float2 b1 = *(const float2*)(qb + 16 * kc + 8 + 2 * i);
            split2(a0.x * 0.125f, a0.y * 0.125f, qh[kc][0], ql[kc][0]);
            split2(b0.x * 0.125f, b0.y * 0.125f, qh[kc][1], ql[kc][1]);
            split2(a1.x * 0.125f, a1.y * 0.125f, qh[kc][2], ql[kc][2]);
            split2(b1.x * 0.125f, b1.y * 0.125f, qh[kc][3], ql[kc][3]);
        }
    }

    const u32* mra = g_mbits + (size_t)(b * S_ + q0 + qw + g) * (S_ / 32);
    const u32* mrb = mra + 8 * (S_ / 32);

    float* arowA = attn ? attn + ((size_t)bh * S_ + q0 + qw + g) * S_ : nullptr;
    float* arowB = arowA ? arowA + 8 * S_ : nullptr;

    float sa = 0.f, sb = 0.f;
    float o[8][4];
    #pragma unroll
    for (int d = 0; d < 8; ++d) o[d][0] = o[d][1] = o[d][2] = o[d][3] = 0.f;

    // =================== single pass: QK -> e -> attn(e) + e@V ===================
    for (int kt = 0; kt < NKT; ++kt) {
        __syncthreads();
        stage_k(Kb + (size_t)kt * 128 * D_, KHI, KLO, tid);
        stage_vt(Vb + (size_t)kt * 128 * D_, VTHI, VTLO, tid);
        __syncthreads();

        #pragma unroll
        for (int sub = 0; sub < 2; ++sub) {
            #pragma unroll
            for (int jq = 0; jq < 2; ++jq) {
                float c[4][4];
                #pragma unroll
                for (int j = 0; j < 4; ++j)
                    c[j][0] = c[j][1] = c[j][2] = c[j][3] = 0.f;

                // ---- QK MMAs for this 32-col group ----
                #pragma unroll
                for (int j4 = 0; j4 < 4; ++j4) {
                    int nrow = sub * 64 + jq * 32 + j4 * 8 + trow;
                    u32 rb = (u32)((nrow * KQ_STR + tmat * 4) * 4);
                    u32 bhv[8], blv[8];
                    ldm4(&bhv[0], khi_u + rb);
                    ldm4(&bhv[4], khi_u + rb + 64);
                    ldm4(&blv[0], klo_u + rb);
                    ldm4(&blv[4], klo_u + rb + 64);
                    #pragma unroll
                    for (int kc = 0; kc < 4; ++kc) {
                        mma16816(c[j4], qh[kc], bhv[2 * kc], bhv[2 * kc + 1]);
                        mma16816(c[j4], qh[kc], blv[2 * kc], blv[2 * kc + 1]);
                        mma16816(c[j4], ql[kc], bhv[2 * kc], bhv[2 * kc + 1]);
                    }
                }

                // ---- mask + exp ----
                u32 wa = mra[kt * 4 + sub * 2 + jq];
                u32 wb = mrb[kt * 4 + sub * 2 + jq];
                #pragma unroll
                for (int j4 = 0; j4 < 4; ++j4) {
                    int sh = j4 * 8 + 2 * i;
                    u32 ba = wa >> sh, bb = wb >> sh;
                    float e0 = (ba & 1u) ? __expf(c[j4][0]) : 0.f;
                    float e1 = (ba & 2u) ? __expf(c[j4][1]) : 0.f;
                    float e2 = (bb & 1u) ? __expf(c[j4][2]) : 0.f;
                    float e3 = (bb & 2u) ? __expf(c[j4][3]) : 0.f;
                    sa += e0 + e1;
                    sb += e2 + e3;
                    c[j4][0] = e0; c[j4][1] = e1; c[j4][2] = e2; c[j4][3] = e3;
                }

                // ---- direct unnormalized attn store (STG.64 per quad-row) ----
                if (arowA) {
                    int colbase = kt * 128 + sub * 64 + jq * 32 + 2 * i;
                    #pragma unroll
                    for (int j4 = 0; j4 < 4; ++j4) {
                        *(float2*)&arowA[colbase + j4 * 8] = make_float2(c[j4][0], c[j4][1]);
                        *(float2*)&arowB[colbase + j4 * 8] = make_float2(c[j4][2], c[j4][3]);
                    }
                }

                // ---- pack e (hi/lo) and accumulate e @ V for these 2 k-chunks ----
                u32 ah[2][4], al[2][4];
                #pragma unroll
                for (int kc2 = 0; kc2 < 2; ++kc2) {
                    split2(c[2 * kc2][0],     c[2 * kc2][1],     ah[kc2][0], al[kc2][0]);
                    split2(c[2 * kc2][2],     c[2 * kc2][3],     ah[kc2][1], al[kc2][1]);
                    split2(c[2 * kc2 + 1][0], c[2 * kc2 + 1][1], ah[kc2][2], al[kc2][2]);
                    split2(c[2 * kc2 + 1][2], c[2 * kc2 + 1][3], ah[kc2][3], al[kc2][3]);
                }
                #pragma unroll
                for (int dblk = 0; dblk < 8; ++dblk) {
                    u32 rb = (u32)(((dblk * 8 + trow) * VT_STR
                                    + sub * 32 + jq * 16 + tmat * 4) * 4);
                    u32 vh[4], vl[4];
                    ldm4(vh, vthi_u + rb);
                    ldm4(vl, vtlo_u + rb);
                    #pragma unroll
                    for (int kc2 = 0; kc2 < 2; ++kc2) {
                        mma16816(o[dblk], ah[kc2], vh[2 * kc2], vh[2 * kc2 + 1]);
                        mma16816(o[dblk], al[kc2], vh[2 * kc2], vh[2 * kc2 + 1]);
                        mma16816(o[dblk], ah[kc2], vl[2 * kc2], vl[2 * kc2 + 1]);
                    }
                }
            }
        }
    }

    // =================== epilogue ===================
    sa += __shfl_xor_sync(0xffffffffu, sa, 1);
    sa += __shfl_xor_sync(0xffffffffu, sa, 2);
    sb += __shfl_xor_sync(0xffffffffu, sb, 1);
    sb += __shfl_xor_sync(0xffffffffu, sb, 2);
    const float inva = (sa > 0.f) ? (1.0f / sa) : 0.f;
    const float invb = (sb > 0.f) ? (1.0f / sb) : 0.f;

    if (i == 0) {
        g_inv[(size_t)bh * S_ + q0 + qw + g]     = inva;
        g_inv[(size_t)bh * S_ + q0 + qw + g + 8] = invb;
    }

    if (outp) {
        float* orowA = outp + ((size_t)bh * S_ + q0 + qw + g) * D_ + 2 * i;
        float* orowB = orowA + 8 * D_;
        #pragma unroll
        for (int dblk = 0; dblk < 8; ++dblk) {
            *(float2*)&orowA[dblk * 8] = make_float2(o[dblk][0] * inva, o[dblk][1] * inva);
            *(float2*)&orowB[dblk * 8] = make_float2(o[dblk][2] * invb, o[dblk][3] * invb);
        }
    }
}

extern "C" void kernel_launch(void* const* d_in, const int* in_sizes, int n_in,
                              void* d_out, int out_size)
{
    const float* Q    = (const float*)d_in[0];
    const float* K    = (const float*)d_in[1];
    const float* V    = (const float*)d_in[2];
    const int*   mask = (const int*)d_in[3];

    const size_t OUT_E  = (size_t)B_ * H_ * S_ * D_;
    const size_t ATTN_E = (size_t)B_ * H_ * S_ * S_;
    float* o = nullptr; float* a = nullptr;
    if ((size_t)out_size >= OUT_E + ATTN_E) { o = (float*)d_out; a = (float*)d_out + OUT_E; }
    else if ((size_t)out_size == ATTN_E)    { a = (float*)d_out; }
    else                                    { o = (float*)d_out; }

    maskbits_kernel<<<(B_ * S_ * (S_ / 32)) / 256, 256>>>(mask);

    cudaFuncSetAttribute(attn_mma, cudaFuncAttributeMaxDynamicSharedMemorySize, SMEM_BYTES);
    dim3 grid(B_ * H_, S_ / 128);
    attn_mma<<<grid, THREADS, SMEM_BYTES>>>(Q, K, V, o, a);

    if (a) {
        size_t n4 = ATTN_E / 4;
        norm_kernel<<<(unsigned)(n4 / 256), 256>>>(a);
    }
}

// round 8
// speedup vs baseline: 1.6073x; 1.0372x over previous
#include <cuda_runtime.h>
#include <cuda_fp16.h>

typedef unsigned int u32;

#define B_ 4
#define H_ 16
#define S_ 2048
#define D_ 64
#define NKT 16
#define THREADS 256
#define KQ_STR 36      // u32 per K smem row (144B stride; conflict-free ldmatrix)
#define VT_STR 68      // u32 per Vt smem row (272B stride; conflict-free ldmatrix)

__device__ u32   g_mbits[(size_t)B_ * S_ * (S_ / 32)];   // 2 MB mask bitfield
__device__ float g_inv[(size_t)B_ * H_ * S_];            // per-row 1/sum
__device__ float g_scratch[(size_t)B_ * H_ * S_ * S_];   // fallback e-buffer (out-only case)

// kernel1 smem: K tiles only
#define SM_KHI  0
#define SM_KLO  (SM_KHI + 128 * KQ_STR * 4)
#define SMEM_K  (SM_KLO + 128 * KQ_STR * 4)              // 36864 B

// kernel2 smem: Vt tiles only
#define SM_VTHI 0
#define SM_VTLO (SM_VTHI + 64 * VT_STR * 4)
#define SMEM_V  (SM_VTLO + 64 * VT_STR * 4)              // 34816 B

__device__ __forceinline__ void mma16816(float c[4], const u32 a[4], u32 b0, u32 b1) {
    asm volatile("mma.sync.aligned.m16n8k16.row.col.f32.f16.f16.f32 "
                 "{%0,%1,%2,%3}, {%4,%5,%6,%7}, {%8,%9}, {%0,%1,%2,%3};"
                 : "+f"(c[0]), "+f"(c[1]), "+f"(c[2]), "+f"(c[3])
                 : "r"(a[0]), "r"(a[1]), "r"(a[2]), "r"(a[3]), "r"(b0), "r"(b1));
}

__device__ __forceinline__ void ldm4(u32* r, u32 addr) {
    asm volatile("ldmatrix.sync.aligned.m8n8.x4.shared.b16 {%0,%1,%2,%3}, [%4];"
                 : "=r"(r[0]), "=r"(r[1]), "=r"(r[2]), "=r"(r[3]) : "r"(addr));
}

__device__ __forceinline__ u32 smem_u32(const void* p) {
    return (u32)__cvta_generic_to_shared(p);
}

// one-instruction f32x2 -> f16x2 pack (cvt.rn.f16x2.f32)
__device__ __forceinline__ void split2(float x, float y, u32& h, u32& l) {
    __half2 H = __floats2half2_rn(x, y);
    h = *reinterpret_cast<u32*>(&H);
    float2 f = __half22float2(H);
    __half2 L = __floats2half2_rn(x - f.x, y - f.y);
    l = *reinterpret_cast<u32*>(&L);
}

// stage 128x64 fp32 row-major K -> hi/lo fp16 smem [128][KQ_STR u32]
__device__ __forceinline__ void stage_k(const float* __restrict__ src,
                                        u32* hi, u32* lo, int tid) {
    const float4* s4 = (const float4*)src;
    #pragma unroll
    for (int it = 0; it < 8; ++it) {
        int idx = it * THREADS + tid;
        int r = idx >> 4, c4 = idx & 15;
        float4 v = s4[idx];
        u32 h0, l0, h1, l1;
        split2(v.x, v.y, h0, l0);
        split2(v.z, v.w, h1, l1);
        int o = r * KQ_STR + c4 * 2;
        *(uint2*)(hi + o) = make_uint2(h0, h1);
        *(uint2*)(lo + o) = make_uint2(l0, l1);
    }
}

// stage 128x64 fp32 V row-major -> transposed hi/lo fp16 smem Vt[64 d][VT_STR u32]
__device__ __forceinline__ void stage_vt(const float* __restrict__ src,
                                         u32* hi, u32* lo, int tid) {
    const float4* s4 = (const float4*)src;
    #pragma unroll
    for (int it = 0; it < 4; ++it) {
        int idx = it * THREADS + tid;
        int d4 = idx & 15, kp = idx >> 4;
        float4 a = s4[(2 * kp) * 16 + d4];
        float4 b = s4[(2 * kp + 1) * 16 + d4];
        float av[4] = {a.x, a.y, a.z, a.w};
        float bv[4] = {b.x, b.y, b.z, b.w};
        #pragma unroll
        for (int dd0 = 0; dd0 < 4; ++dd0) {
            int dd = (dd0 + d4) & 3;               // rotate -> fewer store conflicts
            u32 h, l;
            split2(av[dd], bv[dd], h, l);
            hi[(4 * d4 + dd) * VT_STR + kp] = h;
            lo[(4 * d4 + dd) * VT_STR + kp] = l;
        }
    }
}

__global__ void maskbits_kernel(const int* __restrict__ mask) {
    int w = blockIdx.x * blockDim.x + threadIdx.x;
    const int4* src = (const int4*)mask + (size_t)w * 8;
    u32 bits = 0;
    #pragma unroll
    for (int i = 0; i < 8; ++i) {
        int4 v = src[i];
        bits |= (v.x != 0 ? 1u : 0u) << (i * 4);
        bits |= (v.y != 0 ? 1u : 0u) << (i * 4 + 1);
        bits |= (v.z != 0 ? 1u : 0u) << (i * 4 + 2);
        bits |= (v.w != 0 ? 1u : 0u) << (i * 4 + 3);
    }
    g_mbits[w] = bits;
}

// ============ kernel 1: S=QK^T -> e=exp(masked) -> attn(e) + row sums ============
__global__ __launch_bounds__(THREADS, 2)
void attn_qk(const float* __restrict__ Q, const float* __restrict__ K,
             float* __restrict__ attn)
{
    extern __shared__ char sm[];
    u32* KHI = (u32*)(sm + SM_KHI);
    u32* KLO = (u32*)(sm + SM_KLO);
    const u32 khi_u = smem_u32(KHI), klo_u = smem_u32(KLO);

    const int tid = threadIdx.x, wid = tid >> 5, lane = tid & 31;
    const int g = lane >> 2, i = lane & 3;
    const int trow = lane & 7, tmat = lane >> 3;
    const int bh = blockIdx.x, b = bh >> 4, q0 = blockIdx.y * 128;
    const int qw = wid * 16;

    const float* Kb = K + (size_t)bh * S_ * D_;

    // Q fragments straight from gmem (rows qw+g, qw+g+8), scale folded
    u32 qh[4][4], ql[4][4];
    {
        const float* qa = Q + ((size_t)bh * S_ + q0 + qw + g) * D_;
        const float* qb = qa + 8 * D_;
        #pragma unroll
        for (int kc = 0; kc < 4; ++kc) {
            float2 a0 = *(const float2*)(qa + 16 * kc + 2 * i);
            float2 a1 = *(const float2*)(qa + 16 * kc + 8 + 2 * i);
            float2 b0 = *(const float2*)(qb + 16 * kc + 2 * i);
            float2 b1 = *(const float2*)(qb + 16 * kc + 8 + 2 * i);
            split2(a0.x * 0.125f, a0.y * 0.125f, qh[kc][0], ql[kc][0]);
            split2(b0.x * 0.125f, b0.y * 0.125f, qh[kc][1], ql[kc][1]);
            split2(a1.x * 0.125f, a1.y * 0.125f, qh[kc][2], ql[kc][2]);
            split2(b1.x * 0.125f, b1.y * 0.125f, qh[kc][3], ql[kc][3]);
        }
    }

    const u32* mra = g_mbits + (size_t)(b * S_ + q0 + qw + g) * (S_ / 32);
    const u32* mrb = mra + 8 * (S_ / 32);
    float* arowA = attn + ((size_t)bh * S_ + q0 + qw + g) * S_;
    float* arowB = arowA + 8 * S_;

    float sa = 0.f, sb = 0.f;

    for (int kt = 0; kt < NKT; ++kt) {
        __syncthreads();
        stage_k(Kb + (size_t)kt * 128 * D_, KHI, KLO, tid);
        __syncthreads();

        #pragma unroll
        for (int sub = 0; sub < 2; ++sub) {
            #pragma unroll
            for (int jq = 0; jq < 2; ++jq) {
                float c[4][4];
                #pragma unroll
                for (int j = 0; j < 4; ++j)
                    c[j][0] = c[j][1] = c[j][2] = c[j][3] = 0.f;

                #pragma unroll
                for (int j4 = 0; j4 < 4; ++j4) {
                    int nrow = sub * 64 + jq * 32 + j4 * 8 + trow;
                    u32 rb = (u32)((nrow * KQ_STR + tmat * 4) * 4);
                    u32 bhv[8], blv[8];
                    ldm4(&bhv[0], khi_u + rb);
                    ldm4(&bhv[4], khi_u + rb + 64);
                    ldm4(&blv[0], klo_u + rb);
                    ldm4(&blv[4], klo_u + rb + 64);
                    #pragma unroll
                    for (int kc = 0; kc < 4; ++kc) {
                        mma16816(c[j4], qh[kc], bhv[2 * kc], bhv[2 * kc + 1]);
                        mma16816(c[j4], qh[kc], blv[2 * kc], blv[2 * kc + 1]);
                        mma16816(c[j4], ql[kc], bhv[2 * kc], bhv[2 * kc + 1]);
                    }
                }

                u32 wa = mra[kt * 4 + sub * 2 + jq];
                u32 wb = mrb[kt * 4 + sub * 2 + jq];
                int colbase = kt * 128 + sub * 64 + jq * 32 + 2 * i;
                #pragma unroll
                for (int j4 = 0; j4 < 4; ++j4) {
                    int sh = j4 * 8 + 2 * i;
                    u32 ba = wa >> sh, bb = wb >> sh;
                    float e0 = (ba & 1u) ? __expf(c[j4][0]) : 0.f;
                    float e1 = (ba & 2u) ? __expf(c[j4][1]) : 0.f;
                    float e2 = (bb & 1u) ? __expf(c[j4][2]) : 0.f;
                    float e3 = (bb & 2u) ? __expf(c[j4][3]) : 0.f;
                    sa += e0 + e1;
                    sb += e2 + e3;
                    *(float2*)&arowA[colbase + j4 * 8] = make_float2(e0, e1);
                    *(float2*)&arowB[colbase + j4 * 8] = make_float2(e2, e3);
                }
            }
        }
    }

    sa += __shfl_xor_sync(0xffffffffu, sa, 1);
    sa += __shfl_xor_sync(0xffffffffu, sa, 2);
    sb += __shfl_xor_sync(0xffffffffu, sb, 1);
    sb += __shfl_xor_sync(0xffffffffu, sb, 2);
    if (i == 0) {
        g_inv[(size_t)bh * S_ + q0 + qw + g]     = (sa > 0.f) ? (1.0f / sa) : 0.f;
        g_inv[(size_t)bh * S_ + q0 + qw + g + 8] = (sb > 0.f) ? (1.0f / sb) : 0.f;
    }
}

// ============ kernel 2: normalize attn in-place + P@V -> out ============
__global__ __launch_bounds__(THREADS, 2)
void attn_pv(const float* __restrict__ V, float* __restrict__ outp,
             float* __restrict__ attn)
{
    extern __shared__ char sm[];
    u32* VTHI = (u32*)(sm + SM_VTHI);
    u32* VTLO = (u32*)(sm + SM_VTLO);
    const u32 vthi_u = smem_u32(VTHI), vtlo_u = smem_u32(VTLO);

    const int tid = threadIdx.x, wid = tid >> 5, lane = tid & 31;
    const int g = lane >> 2, i = lane & 3;
    const int trow = lane & 7, tmat = lane >> 3;
    const int bh = blockIdx.x, q0 = blockIdx.y * 128;
    const int qw = wid * 16;

    const float* Vb = V + (size_t)bh * S_ * D_;
    float* arowA = attn + ((size_t)bh * S_ + q0 + qw + g) * S_;
    float* arowB = arowA + 8 * S_;

    const float inva = __ldg(&g_inv[(size_t)bh * S_ + q0 + qw + g]);
    const float invb = __ldg(&g_inv[(size_t)bh * S_ + q0 + qw + g + 8]);

    float o[8][4];
    #pragma unroll
    for (int d = 0; d < 8; ++d) o[d][0] = o[d][1] = o[d][2] = o[d][3] = 0.f;

    for (int kt = 0; kt < NKT; ++kt) {
        __syncthreads();
        stage_vt(Vb + (size_t)kt * 128 * D_, VTHI, VTLO, tid);
        __syncthreads();

        #pragma unroll
        for (int sub = 0; sub < 2; ++sub) {
            #pragma unroll
            for (int jq = 0; jq < 2; ++jq) {
                int colbase = kt * 128 + sub * 64 + jq * 32 + 2 * i;

                // load e-frags (mirror of kernel1's store), normalize, store back, split
                u32 ah[2][4], al[2][4];
                #pragma unroll
                for (int kc2 = 0; kc2 < 2; ++kc2) {
                    float2 pa0 = *(float2*)&arowA[colbase + kc2 * 16];
                    float2 pb0 = *(float2*)&arowB[colbase + kc2 * 16];
                    float2 pa1 = *(float2*)&arowA[colbase + kc2 * 16 + 8];
                    float2 pb1 = *(float2*)&arowB[colbase + kc2 * 16 + 8];
                    pa0.x *= inva; pa0.y *= inva; pa1.x *= inva; pa1.y *= inva;
                    pb0.x *= invb; pb0.y *= invb; pb1.x *= invb; pb1.y *= invb;
                    *(float2*)&arowA[colbase + kc2 * 16]     = pa0;
                    *(float2*)&arowB[colbase + kc2 * 16]     = pb0;
                    *(float2*)&arowA[colbase + kc2 * 16 + 8] = pa1;
                    *(float2*)&arowB[colbase + kc2 * 16 + 8] = pb1;
                    split2(pa0.x, pa0.y, ah[kc2][0], al[kc2][0]);
                    split2(pb0.x, pb0.y, ah[kc2][1], al[kc2][1]);
                    split2(pa1.x, pa1.y, ah[kc2][2], al[kc2][2]);
                    split2(pb1.x, pb1.y, ah[kc2][3], al[kc2][3]);
                }

                #pragma unroll
                for (int dblk = 0; dblk < 8; ++dblk) {
                    u32 rb = (u32)(((dblk * 8 + trow) * VT_STR
                                    + sub * 32 + jq * 16 + tmat * 4) * 4);
                    u32 vh[4], vl[4];
                    ldm4(vh, vthi_u + rb);
                    ldm4(vl, vtlo_u + rb);
                    #pragma unroll
                    for (int kc2 = 0; kc2 < 2; ++kc2) {
                        mma16816(o[dblk], ah[kc2], vh[2 * kc2], vh[2 * kc2 + 1]);
                        mma16816(o[dblk], al[kc2], vh[2 * kc2], vh[2 * kc2 + 1]);
                        mma16816(o[dblk], ah[kc2], vl[2 * kc2], vl[2 * kc2 + 1]);
                    }
                }
            }
        }
    }

    if (outp) {
        float* orowA = outp + ((size_t)bh * S_ + q0 + qw + g) * D_ + 2 * i;
        float* orowB = orowA + 8 * D_;
        #pragma unroll
        for (int dblk = 0; dblk < 8; ++dblk) {
            *(float2*)&orowA[dblk * 8] = make_float2(o[dblk][0], o[dblk][1]);
            *(float2*)&orowB[dblk * 8] = make_float2(o[dblk][2], o[dblk][3]);
        }
    }
}

extern "C" void kernel_launch(void* const* d_in, const int* in_sizes, int n_in,
                              void* d_out, int out_size)
{
    const float* Q    = (const float*)d_in[0];
    const float* K    = (const float*)d_in[1];
    const float* V    = (const float*)d_in[2];
    const int*   mask = (const int*)d_in[3];

    const size_t OUT_E  = (size_t)B_ * H_ * S_ * D_;
    const size_t ATTN_E = (size_t)B_ * H_ * S_ * S_;
    float* o = nullptr; float* a = nullptr;
    if ((size_t)out_size >= OUT_E + ATTN_E) { o = (float*)d_out; a = (float*)d_out + OUT_E; }
    else if ((size_t)out_size == ATTN_E)    { a = (float*)d_out; }
    else                                    { o = (float*)d_out; }

    if (!a) {  // out-only: use device scratch as e-buffer
        cudaGetSymbolAddress((void**)&a, g_scratch);
    }

    maskbits_kernel<<<(B_ * S_ * (S_ / 32)) / 256, 256>>>(mask);

    cudaFuncSetAttribute(attn_qk, cudaFuncAttributeMaxDynamicSharedMemorySize, SMEM_K);
    cudaFuncSetAttribute(attn_pv, cudaFuncAttributeMaxDynamicSharedMemorySize, SMEM_V);

    dim3 grid(B_ * H_, S_ / 128);
    attn_qk<<<grid, THREADS, SMEM_K>>>(Q, K, a);
    attn_pv<<<grid, THREADS, SMEM_V>>>(V, o, a);
}

// round 9
// speedup vs baseline: 1.6999x; 1.0576x over previous
#include <cuda_runtime.h>
#include <cuda_fp16.h>

typedef unsigned int u32;

#define B_ 4
#define H_ 16
#define S_ 2048
#define D_ 64
#define NKT 16
#define THREADS 256
#define KQ_STR 36      // u32 per K smem row (144B stride; conflict-free ldmatrix)
#define VT_STR 68      // u32 per Vt smem row (272B stride; conflict-free ldmatrix)

__device__ u32   g_mbits[(size_t)B_ * S_ * (S_ / 32)];   // 2 MB mask bitfield
__device__ float g_inv[(size_t)B_ * H_ * S_];            // per-row 1/sum
__device__ float g_scratch[(size_t)B_ * H_ * S_ * S_];   // fallback e-buffer (out-only case)

// kernel1 smem: double-buffered K tiles
#define KBUF   (128 * KQ_STR * 4)                        // 18432 B per (hi|lo)
#define SMEM_K (4 * KBUF)                                // 73728 B  (2 bufs x hi/lo)
// kernel2 smem: double-buffered Vt tiles
#define VBUF   (64 * VT_STR * 4)                         // 17408 B per (hi|lo)
#define SMEM_V (4 * VBUF)                                // 69632 B

__device__ __forceinline__ void mma16816(float c[4], const u32 a[4], u32 b0, u32 b1) {
    asm volatile("mma.sync.aligned.m16n8k16.row.col.f32.f16.f16.f32 "
                 "{%0,%1,%2,%3}, {%4,%5,%6,%7}, {%8,%9}, {%0,%1,%2,%3};"
                 : "+f"(c[0]), "+f"(c[1]), "+f"(c[2]), "+f"(c[3])
                 : "r"(a[0]), "r"(a[1]), "r"(a[2]), "r"(a[3]), "r"(b0), "r"(b1));
}

__device__ __forceinline__ void ldm4(u32* r, u32 addr) {
    asm volatile("ldmatrix.sync.aligned.m8n8.x4.shared.b16 {%0,%1,%2,%3}, [%4];"
                 : "=r"(r[0]), "=r"(r[1]), "=r"(r[2]), "=r"(r[3]) : "r"(addr));
}

__device__ __forceinline__ u32 smem_u32(const void* p) {
    return (u32)__cvta_generic_to_shared(p);
}

// one-instruction f32x2 -> f16x2 pack (cvt.rn.f16x2.f32) + residual
__device__ __forceinline__ void split2(float x, float y, u32& h, u32& l) {
    __half2 H = __floats2half2_rn(x, y);
    h = *reinterpret_cast<u32*>(&H);
    float2 f = __half22float2(H);
    __half2 L = __floats2half2_rn(x - f.x, y - f.y);
    l = *reinterpret_cast<u32*>(&L);
}

// stage 128x64 fp32 row-major K -> hi/lo fp16 smem [128][KQ_STR u32]
__device__ __forceinline__ void stage_k(const float* __restrict__ src,
                                        u32* hi, u32* lo, int tid) {
    const float4* s4 = (const float4*)src;
    #pragma unroll
    for (int it = 0; it < 8; ++it) {
        int idx = it * THREADS + tid;
        int r = idx >> 4, c4 = idx & 15;
        float4 v = s4[idx];
        u32 h0, l0, h1, l1;
        split2(v.x, v.y, h0, l0);
        split2(v.z, v.w, h1, l1);
        int o = r * KQ_STR + c4 * 2;
        *(uint2*)(hi + o) = make_uint2(h0, h1);
        *(uint2*)(lo + o) = make_uint2(l0, l1);
    }
}

// stage 128x64 fp32 V row-major -> transposed hi/lo fp16 smem Vt[64 d][VT_STR u32]
__device__ __forceinline__ void stage_vt(const float* __restrict__ src,
                                         u32* hi, u32* lo, int tid) {
    const float4* s4 = (const float4*)src;
    #pragma unroll
    for (int it = 0; it < 4; ++it) {
        int idx = it * THREADS + tid;
        int d4 = idx & 15, kp = idx >> 4;
        float4 a = s4[(2 * kp) * 16 + d4];
        float4 b = s4[(2 * kp + 1) * 16 + d4];
        float av[4] = {a.x, a.y, a.z, a.w};
        float bv[4] = {b.x, b.y, b.z, b.w};
        #pragma unroll
        for (int dd0 = 0; dd0 < 4; ++dd0) {
            int dd = (dd0 + d4) & 3;               // rotate -> fewer store conflicts
            u32 h, l;
            split2(av[dd], bv[dd], h, l);
            hi[(4 * d4 + dd) * VT_STR + kp] = h;
            lo[(4 * d4 + dd) * VT_STR + kp] = l;
        }
    }
}

__global__ void maskbits_kernel(const int* __restrict__ mask) {
    int w = blockIdx.x * blockDim.x + threadIdx.x;
    const int4* src = (const int4*)mask + (size_t)w * 8;
    u32 bits = 0;
    #pragma unroll
    for (int i = 0; i < 8; ++i) {
        int4 v = src[i];
        bits |= (v.x != 0 ? 1u : 0u) << (i * 4);
        bits |= (v.y != 0 ? 1u : 0u) << (i * 4 + 1);
        bits |= (v.z != 0 ? 1u : 0u) << (i * 4 + 2);
        bits |= (v.w != 0 ? 1u : 0u) << (i * 4 + 3);
    }
    g_mbits[w] = bits;
}

// ============ kernel 1: S=QK^T -> e=exp(masked) -> attn(e) + row sums ============
__global__ __launch_bounds__(THREADS, 2)
void attn_qk(const float* __restrict__ Q, const float* __restrict__ K,
             float* __restrict__ attn)
{
    extern __shared__ char sm[];

    const int tid = threadIdx.x, wid = tid >> 5, lane = tid & 31;
    const int g = lane >> 2, i = lane & 3;
    const int trow = lane & 7, tmat = lane >> 3;
    const int q0 = blockIdx.x * 128, bh = blockIdx.y, b = bh >> 4;
    const int qw = wid * 16;

    const float* Kb = K + (size_t)bh * S_ * D_;

    // Q fragments straight from gmem (rows qw+g, qw+g+8), scale folded
    u32 qh[4][4], ql[4][4];
    {
        const float* qa = Q + ((size_t)bh * S_ + q0 + qw + g) * D_;
        const float* qb = qa + 8 * D_;
        #pragma unroll
        for (int kc = 0; kc < 4; ++kc) {
            float2 a0 = *(const float2*)(qa + 16 * kc + 2 * i);
            float2 a1 = *(const float2*)(qa + 16 * kc + 8 + 2 * i);
            float2 b0 = *(const float2*)(qb + 16 * kc + 2 * i);
            float2 b1 = *(const float2*)(qb + 16 * kc + 8 + 2 * i);
            split2(a0.x * 0.125f, a0.y * 0.125f, qh[kc][0], ql[kc][0]);
            split2(b0.x * 0.125f, b0.y * 0.125f, qh[kc][1], ql[kc][1]);
            split2(a1.x * 0.125f, a1.y * 0.125f, qh[kc][2], ql[kc][2]);
            split2(b1.x * 0.125f, b1.y * 0.125f, qh[kc][3], ql[kc][3]);
        }
    }

    const u32* mra = g_mbits + (size_t)(b * S_ + q0 + qw + g) * (S_ / 32);
    const u32* mrb = mra + 8 * (S_ / 32);
    float* arowA = attn + ((size_t)bh * S_ + q0 + qw + g) * S_;
    float* arowB = arowA + 8 * S_;

    float sa = 0.f, sb = 0.f;

    // prologue: stage tile 0 into buffer 0
    stage_k(Kb, (u32*)(sm + 0), (u32*)(sm + KBUF), tid);
    __syncthreads();

    for (int kt = 0; kt < NKT; ++kt) {
        const int bsel = (kt & 1) * 2 * KBUF;
        const u32 khi_u = smem_u32(sm + bsel);
        const u32 klo_u = khi_u + KBUF;

        #pragma unroll
        for (int sub = 0; sub < 2; ++sub) {
            #pragma unroll
            for (int jq = 0; jq < 2; ++jq) {
                float c[4][4];
                #pragma unroll
                for (int j = 0; j < 4; ++j)
                    c[j][0] = c[j][1] = c[j][2] = c[j][3] = 0.f;

                #pragma unroll
                for (int j4 = 0; j4 < 4; ++j4) {
                    int nrow = sub * 64 + jq * 32 + j4 * 8 + trow;
                    u32 rb = (u32)((nrow * KQ_STR + tmat * 4) * 4);
                    u32 bhv[8], blv[8];
                    ldm4(&bhv[0], khi_u + rb);
                    ldm4(&bhv[4], khi_u + rb + 64);
                    ldm4(&blv[0], klo_u + rb);
                    ldm4(&blv[4], klo_u + rb + 64);
                    #pragma unroll
                    for (int kc = 0; kc < 4; ++kc) {
                        mma16816(c[j4], qh[kc], bhv[2 * kc], bhv[2 * kc + 1]);
                        mma16816(c[j4], qh[kc], blv[2 * kc], blv[2 * kc + 1]);
                        mma16816(c[j4], ql[kc], bhv[2 * kc], bhv[2 * kc + 1]);
                    }
                }

                u32 wa = mra[kt * 4 + sub * 2 + jq];
                u32 wb = mrb[kt * 4 + sub * 2 + jq];
                int colbase = kt * 128 + sub * 64 + jq * 32 + 2 * i;
                #pragma unroll
                for (int j4 = 0; j4 < 4; ++j4) {
                    int sh = j4 * 8 + 2 * i;
                    u32 ba = wa >> sh, bb = wb >> sh;
                    float e0 = (ba & 1u) ? __expf(c[j4][0]) : 0.f;
                    float e1 = (ba & 2u) ? __expf(c[j4][1]) : 0.f;
                    float e2 = (bb & 1u) ? __expf(c[j4][2]) : 0.f;
                    float e3 = (bb & 2u) ? __expf(c[j4][3]) : 0.f;
                    sa += e0 + e1;
                    sb += e2 + e3;
                    __stcs((float2*)&arowA[colbase + j4 * 8], make_float2(e0, e1));
                    __stcs((float2*)&arowB[colbase + j4 * 8], make_float2(e2, e3));
                }
            }
        }

        // stage next tile into the other buffer (overlaps with other warps' compute)
        if (kt + 1 < NKT) {
            const int nsel = ((kt + 1) & 1) * 2 * KBUF;
            stage_k(Kb + (size_t)(kt + 1) * 128 * D_,
                    (u32*)(sm + nsel), (u32*)(sm + nsel + KBUF), tid);
        }
        __syncthreads();
    }

    sa += __shfl_xor_sync(0xffffffffu, sa, 1);
    sa += __shfl_xor_sync(0xffffffffu, sa, 2);
    sb += __shfl_xor_sync(0xffffffffu, sb, 1);
    sb += __shfl_xor_sync(0xffffffffu, sb, 2);
    if (i == 0) {
        g_inv[(size_t)bh * S_ + q0 + qw + g]     = (sa > 0.f) ? (1.0f / sa) : 0.f;
        g_inv[(size_t)bh * S_ + q0 + qw + g + 8] = (sb > 0.f) ? (1.0f / sb) : 0.f;
    }
}

// ============ kernel 2: normalize attn in-place + P@V -> out ============
__global__ __launch_bounds__(THREADS, 2)
void attn_pv(const float* __restrict__ V, float* __restrict__ outp,
             float* __restrict__ attn)
{
    extern __shared__ char sm[];

    const int tid = threadIdx.x, wid = tid >> 5, lane = tid & 31;
    const int g = lane >> 2, i = lane & 3;
    const int trow = lane & 7, tmat = lane >> 3;
    const int q0 = blockIdx.x * 128, bh = blockIdx.y;
    const int qw = wid * 16;

    const float* Vb = V + (size_t)bh * S_ * D_;
    float* arowA = attn + ((size_t)bh * S_ + q0 + qw + g) * S_;
    float* arowB = arowA + 8 * S_;

    const float inva = __ldg(&g_inv[(size_t)bh * S_ + q0 + qw + g]);
    const float invb = __ldg(&g_inv[(size_t)bh * S_ + q0 + qw + g + 8]);

    float o[8][4];
    #pragma unroll
    for (int d = 0; d < 8; ++d) o[d][0] = o[d][1] = o[d][2] = o[d][3] = 0.f;

    stage_vt(Vb, (u32*)(sm + 0), (u32*)(sm + VBUF), tid);
    __syncthreads();

    for (int kt = 0; kt < NKT; ++kt) {
        const int bsel = (kt & 1) * 2 * VBUF;
        const u32 vthi_u = smem_u32(sm + bsel);
        const u32 vtlo_u = vthi_u + VBUF;

        #pragma unroll
        for (int sub = 0; sub < 2; ++sub) {
            #pragma unroll
            for (int jq = 0; jq < 2; ++jq) {
                int colbase = kt * 128 + sub * 64 + jq * 32 + 2 * i;

                // streaming e-load, normalize, streaming store, split to fp16 hi/lo
                u32 ah[2][4], al[2][4];
                #pragma unroll
                for (int kc2 = 0; kc2 < 2; ++kc2) {
                    float2 pa0 = __ldcs((const float2*)&arowA[colbase + kc2 * 16]);
                    float2 pb0 = __ldcs((const float2*)&arowB[colbase + kc2 * 16]);
                    float2 pa1 = __ldcs((const float2*)&arowA[colbase + kc2 * 16 + 8]);
                    float2 pb1 = __ldcs((const float2*)&arowB[colbase + kc2 * 16 + 8]);
                    pa0.x *= inva; pa0.y *= inva; pa1.x *= inva; pa1.y *= inva;
                    pb0.x *= invb; pb0.y *= invb; pb1.x *= invb; pb1.y *= invb;
                    __stcs((float2*)&arowA[colbase + kc2 * 16],     pa0);
                    __stcs((float2*)&arowB[colbase + kc2 * 16],     pb0);
                    __stcs((float2*)&arowA[colbase + kc2 * 16 + 8], pa1);
                    __stcs((float2*)&arowB[colbase + kc2 * 16 + 8], pb1);
                    split2(pa0.x, pa0.y, ah[kc2][0], al[kc2][0]);
                    split2(pb0.x, pb0.y, ah[kc2][1], al[kc2][1]);
                    split2(pa1.x, pa1.y, ah[kc2][2], al[kc2][2]);
                    split2(pb1.x, pb1.y, ah[kc2][3], al[kc2][3]);
                }

                #pragma unroll
                for (int dblk = 0; dblk < 8; ++dblk) {
                    u32 rb = (u32)(((dblk * 8 + trow) * VT_STR
                                    + sub * 32 + jq * 16 + tmat * 4) * 4);
                    u32 vh[4], vl[4];
                    ldm4(vh, vthi_u + rb);
                    ldm4(vl, vtlo_u + rb);
                    #pragma unroll
                    for (int kc2 = 0; kc2 < 2; ++kc2) {
                        mma16816(o[dblk], ah[kc2], vh[2 * kc2], vh[2 * kc2 + 1]);
                        mma16816(o[dblk], al[kc2], vh[2 * kc2], vh[2 * kc2 + 1]);
                        mma16816(o[dblk], ah[kc2], vl[2 * kc2], vl[2 * kc2 + 1]);
                    }
                }
            }
        }

        if (kt + 1 < NKT) {
            const int nsel = ((kt + 1) & 1) * 2 * VBUF;
            stage_vt(Vb + (size_t)(kt + 1) * 128 * D_,
                     (u32*)(sm + nsel), (u32*)(sm + nsel + VBUF), tid);
        }
        __syncthreads();
    }

    if (outp) {
        float* orowA = outp + ((size_t)bh * S_ + q0 + qw + g) * D_ + 2 * i;
        float* orowB = orowA + 8 * D_;
        #pragma unroll
        for (int dblk = 0; dblk < 8; ++dblk) {
            *(float2*)&orowA[dblk * 8] = make_float2(o[dblk][0], o[dblk][1]);
            *(float2*)&orowB[dblk * 8] = make_float2(o[dblk][2], o[dblk][3]);
        }
    }
}

extern "C" void kernel_launch(void* const* d_in, const int* in_sizes, int n_in,
                              void* d_out, int out_size)
{
    const float* Q    = (const float*)d_in[0];
    const float* K    = (const float*)d_in[1];
    const float* V    = (const float*)d_in[2];
    const int*   mask = (const int*)d_in[3];

    const size_t OUT_E  = (size_t)B_ * H_ * S_ * D_;
    const size_t ATTN_E = (size_t)B_ * H_ * S_ * S_;
    float* o = nullptr; float* a = nullptr;
    if ((size_t)out_size >= OUT_E + ATTN_E) { o = (float*)d_out; a = (float*)d_out + OUT_E; }
    else if ((size_t)out_size == ATTN_E)    { a = (float*)d_out; }
    else                                    { o = (float*)d_out; }

    if (!a) {  // out-only: use device scratch as e-buffer
        cudaGetSymbolAddress((void**)&a, g_scratch);
    }

    maskbits_kernel<<<(B_ * S_ * (S_ / 32)) / 256, 256>>>(mask);

    cudaFuncSetAttribute(attn_qk, cudaFuncAttributeMaxDynamicSharedMemorySize, SMEM_K);
    cudaFuncSetAttribute(attn_pv, cudaFuncAttributeMaxDynamicSharedMemorySize, SMEM_V);

    dim3 grid(S_ / 128, B_ * H_);        // x = q-tile (fast), y = bh -> wavefront shares K/V
    attn_qk<<<grid, THREADS, SMEM_K>>>(Q, K, a);
    attn_pv<<<grid, THREADS, SMEM_V>>>(V, o, a);
}

// round 10
// speedup vs baseline: 1.7711x; 1.0419x over previous
#include <cuda_runtime.h>
#include <cuda_fp16.h>

typedef unsigned int u32;

#define B_ 4
#define H_ 16
#define S_ 2048
#define D_ 64
#define NKT 16
#define THREADS 256
#define KQ_STR 36      // u32 per K smem row (144B stride; conflict-free ldmatrix)
#define VT_STR 68      // u32 per Vt smem row (272B stride; conflict-free ldmatrix)

__device__ u32   g_mbits[(size_t)B_ * S_ * (S_ / 32)];     // 2 MB mask bitfield
__device__ float g_inv[(size_t)B_ * H_ * S_];              // per-row 1/sum
__device__ u32   g_ebuf[(size_t)B_ * H_ * S_ * (S_ / 2)];  // 0.54 GB fp16x2 e-buffer

// kernel1 smem: double-buffered K tiles
#define KBUF   (128 * KQ_STR * 4)
#define SMEM_K (4 * KBUF)                                  // 73728 B -> 2 CTAs/SM
// kernel2 smem: double-buffered Vt tiles
#define VBUF   (64 * VT_STR * 4)
#define SMEM_V (4 * VBUF)                                  // 69632 B -> 2 CTAs/SM

__device__ __forceinline__ void mma16816(float c[4], const u32 a[4], u32 b0, u32 b1) {
    asm volatile("mma.sync.aligned.m16n8k16.row.col.f32.f16.f16.f32 "
                 "{%0,%1,%2,%3}, {%4,%5,%6,%7}, {%8,%9}, {%0,%1,%2,%3};"
                 : "+f"(c[0]), "+f"(c[1]), "+f"(c[2]), "+f"(c[3])
                 : "r"(a[0]), "r"(a[1]), "r"(a[2]), "r"(a[3]), "r"(b0), "r"(b1));
}

__device__ __forceinline__ void ldm4(u32* r, u32 addr) {
    asm volatile("ldmatrix.sync.aligned.m8n8.x4.shared.b16 {%0,%1,%2,%3}, [%4];"
                 : "=r"(r[0]), "=r"(r[1]), "=r"(r[2]), "=r"(r[3]) : "r"(addr));
}

__device__ __forceinline__ u32 smem_u32(const void* p) {
    return (u32)__cvta_generic_to_shared(p);
}

// f32x2 -> packed f16x2 hi + residual lo
__device__ __forceinline__ void split2(float x, float y, u32& h, u32& l) {
    __half2 H = __floats2half2_rn(x, y);
    h = *reinterpret_cast<u32*>(&H);
    float2 f = __half22float2(H);
    __half2 L = __floats2half2_rn(x - f.x, y - f.y);
    l = *reinterpret_cast<u32*>(&L);
}

__device__ __forceinline__ u32 pack_h2(float x, float y) {
    __half2 H = __floats2half2_rn(x, y);
    return *reinterpret_cast<u32*>(&H);
}
__device__ __forceinline__ float2 unpack_h2(u32 v) {
    return __half22float2(*reinterpret_cast<__half2*>(&v));
}

// stage 128x64 fp32 row-major K -> hi/lo fp16 smem [128][KQ_STR u32]
__device__ __forceinline__ void stage_k(const float* __restrict__ src,
                                        u32* hi, u32* lo, int tid) {
    const float4* s4 = (const float4*)src;
    #pragma unroll
    for (int it = 0; it < 8; ++it) {
        int idx = it * THREADS + tid;
        int r = idx >> 4, c4 = idx & 15;
        float4 v = s4[idx];
        u32 h0, l0, h1, l1;
        split2(v.x, v.y, h0, l0);
        split2(v.z, v.w, h1, l1);
        int o = r * KQ_STR + c4 * 2;
        *(uint2*)(hi + o) = make_uint2(h0, h1);
        *(uint2*)(lo + o) = make_uint2(l0, l1);
    }
}

// stage 128x64 fp32 V row-major -> transposed hi/lo fp16 smem Vt[64 d][VT_STR u32]
__device__ __forceinline__ void stage_vt(const float* __restrict__ src,
                                         u32* hi, u32* lo, int tid) {
    const float4* s4 = (const float4*)src;
    #pragma unroll
    for (int it = 0; it < 4; ++it) {
        int idx = it * THREADS + tid;
        int d4 = idx & 15, kp = idx >> 4;
        float4 a = s4[(2 * kp) * 16 + d4];
        float4 b = s4[(2 * kp + 1) * 16 + d4];
        float av[4] = {a.x, a.y, a.z, a.w};
        float bv[4] = {b.x, b.y, b.z, b.w};
        #pragma unroll
        for (int dd0 = 0; dd0 < 4; ++dd0) {
            int dd = (dd0 + d4) & 3;
            u32 h, l;
            split2(av[dd], bv[dd], h, l);
            hi[(4 * d4 + dd) * VT_STR + kp] = h;
            lo[(4 * d4 + dd) * VT_STR + kp] = l;
        }
    }
}

__global__ void maskbits_kernel(const int* __restrict__ mask) {
    int w = blockIdx.x * blockDim.x + threadIdx.x;
    const int4* src = (const int4*)mask + (size_t)w * 8;
    u32 bits = 0;
    #pragma unroll
    for (int i = 0; i < 8; ++i) {
        int4 v = src[i];
        bits |= (v.x != 0 ? 1u : 0u) << (i * 4);
        bits |= (v.y != 0 ? 1u : 0u) << (i * 4 + 1);
        bits |= (v.z != 0 ? 1u : 0u) << (i * 4 + 2);
        bits |= (v.w != 0 ? 1u : 0u) << (i * 4 + 3);
    }
    g_mbits[w] = bits;
}

// ============ kernel 1: S=QK^T -> e=exp(masked) -> fp16 e-buffer + row sums ============
__global__ __launch_bounds__(THREADS, 2)
void attn_qk(const float* __restrict__ Q, const float* __restrict__ K)
{
    extern __shared__ char sm[];

    const int tid = threadIdx.x, wid = tid >> 5, lane = tid & 31;
    const int g = lane >> 2, i = lane & 3;
    const int trow = lane & 7, tmat = lane >> 3;
    const int q0 = blockIdx.x * 128, bh = blockIdx.y, b = bh >> 4;
    const int qw = wid * 16;

    const float* Kb = K + (size_t)bh * S_ * D_;

    u32 qh[4][4], ql[4][4];
    {
        const float* qa = Q + ((size_t)bh * S_ + q0 + qw + g) * D_;
        const float* qb = qa + 8 * D_;
        #pragma unroll
        for (int kc = 0; kc < 4; ++kc) {
            float2 a0 = *(const float2*)(qa + 16 * kc + 2 * i);
            float2 a1 = *(const float2*)(qa + 16 * kc + 8 + 2 * i);
            float2 b0 = *(const float2*)(qb + 16 * kc + 2 * i);
            float2 b1 = *(const float2*)(qb + 16 * kc + 8 + 2 * i);
            split2(a0.x * 0.125f, a0.y * 0.125f, qh[kc][0], ql[kc][0]);
            split2(b0.x * 0.125f, b0.y * 0.125f, qh[kc][1], ql[kc][1]);
            split2(a1.x * 0.125f, a1.y * 0.125f, qh[kc][2], ql[kc][2]);
            split2(b1.x * 0.125f, b1.y * 0.125f, qh[kc][3], ql[kc][3]);
        }
    }

    const u32* mra = g_mbits + (size_t)(b * S_ + q0 + qw + g) * (S_ / 32);
    const u32* mrb = mra + 8 * (S_ / 32);
    u32* ebA = g_ebuf + (size_t)(bh * S_ + q0 + qw + g) * (S_ / 2);
    u32* ebB = ebA + 8 * (S_ / 2);

    float sa = 0.f, sb = 0.f;

    stage_k(Kb, (u32*)(sm + 0), (u32*)(sm + KBUF), tid);
    __syncthreads();

    for (int kt = 0; kt < NKT; ++kt) {
        const int bsel = (kt & 1) * 2 * KBUF;
        const u32 khi_u = smem_u32(sm + bsel);
        const u32 klo_u = khi_u + KBUF;

        #pragma unroll
        for (int sub = 0; sub < 2; ++sub) {
            #pragma unroll
            for (int jq = 0; jq < 2; ++jq) {
                float c[4][4];
                #pragma unroll
                for (int j = 0; j < 4; ++j)
                    c[j][0] = c[j][1] = c[j][2] = c[j][3] = 0.f;

                #pragma unroll
                for (int j4 = 0; j4 < 4; ++j4) {
                    int nrow = sub * 64 + jq * 32 + j4 * 8 + trow;
                    u32 rb = (u32)((nrow * KQ_STR + tmat * 4) * 4);
                    u32 bhv[8], blv[8];
                    ldm4(&bhv[0], khi_u + rb);
                    ldm4(&bhv[4], khi_u + rb + 64);
                    ldm4(&blv[0], klo_u + rb);
                    ldm4(&blv[4], klo_u + rb + 64);
                    #pragma unroll
                    for (int kc = 0; kc < 4; ++kc) {
                        mma16816(c[j4], qh[kc], bhv[2 * kc], bhv[2 * kc + 1]);
                        mma16816(c[j4], qh[kc], blv[2 * kc], blv[2 * kc + 1]);
                        mma16816(c[j4], ql[kc], bhv[2 * kc], bhv[2 * kc + 1]);
                    }
                }

                u32 wa = mra[kt * 4 + sub * 2 + jq];
                u32 wb = mrb[kt * 4 + sub * 2 + jq];
                int ubase = kt * 64 + sub * 32 + jq * 16 + i;      // u32 index
                #pragma unroll
                for (int j4 = 0; j4 < 4; ++j4) {
                    int sh = j4 * 8 + 2 * i;
                    u32 ba = wa >> sh, bb = wb >> sh;
                    float e0 = (ba & 1u) ? __expf(c[j4][0]) : 0.f;
                    float e1 = (ba & 2u) ? __expf(c[j4][1]) : 0.f;
                    float e2 = (bb & 1u) ? __expf(c[j4][2]) : 0.f;
                    float e3 = (bb & 2u) ? __expf(c[j4][3]) : 0.f;
                    sa += e0 + e1;
                    sb += e2 + e3;
                    __stcs(&ebA[ubase + j4 * 4], pack_h2(e0, e1));
                    __stcs(&ebB[ubase + j4 * 4], pack_h2(e2, e3));
                }
            }
        }

        if (kt + 1 < NKT) {
            const int nsel = ((kt + 1) & 1) * 2 * KBUF;
            stage_k(Kb + (size_t)(kt + 1) * 128 * D_,
                    (u32*)(sm + nsel), (u32*)(sm + nsel + KBUF), tid);
        }
        __syncthreads();
    }

    sa += __shfl_xor_sync(0xffffffffu, sa, 1);
    sa += __shfl_xor_sync(0xffffffffu, sa, 2);
    sb += __shfl_xor_sync(0xffffffffu, sb, 1);
    sb += __shfl_xor_sync(0xffffffffu, sb, 2);
    if (i == 0) {
        g_inv[(size_t)bh * S_ + q0 + qw + g]     = (sa > 0.f) ? (1.0f / sa) : 0.f;
        g_inv[(size_t)bh * S_ + q0 + qw + g + 8] = (sb > 0.f) ? (1.0f / sb) : 0.f;
    }
}

// ============ kernel 2: attn = e*inv (fp32) + (e @ V)*inv -> out ============
__global__ __launch_bounds__(THREADS, 2)
void attn_pv(const float* __restrict__ V, float* __restrict__ outp,
             float* __restrict__ attn)
{
    extern __shared__ char sm[];

    const int tid = threadIdx.x, wid = tid >> 5, lane = tid & 31;
    const int g = lane >> 2, i = lane & 3;
    const int trow = lane & 7, tmat = lane >> 3;
    const int q0 = blockIdx.x * 128, bh = blockIdx.y;
    const int qw = wid * 16;

    const float* Vb = V + (size_t)bh * S_ * D_;
    const u32* ebA = g_ebuf + (size_t)(bh * S_ + q0 + qw + g) * (S_ / 2);
    const u32* ebB = ebA + 8 * (S_ / 2);
    float* arowA = attn ? attn + ((size_t)bh * S_ + q0 + qw + g) * S_ : nullptr;
    float* arowB = arowA + 8 * S_;

    const float inva = __ldg(&g_inv[(size_t)bh * S_ + q0 + qw + g]);
    const float invb = __ldg(&g_inv[(size_t)bh * S_ + q0 + qw + g + 8]);

    float o[8][4];
    #pragma unroll
    for (int d = 0; d < 8; ++d) o[d][0] = o[d][1] = o[d][2] = o[d][3] = 0.f;

    stage_vt(Vb, (u32*)(sm + 0), (u32*)(sm + VBUF), tid);
    __syncthreads();

    for (int kt = 0; kt < NKT; ++kt) {
        const int bsel = (kt & 1) * 2 * VBUF;
        const u32 vthi_u = smem_u32(sm + bsel);
        const u32 vtlo_u = vthi_u + VBUF;

        #pragma unroll
        for (int sub = 0; sub < 2; ++sub) {
            #pragma unroll
            for (int jq = 0; jq < 2; ++jq) {
                const int grp = kt * 64 + sub * 32 + jq * 16;      // u32 index base

                // e-fragments: the loaded u32s ARE the fp16 A-fragments
                u32 aa[2][4];
                #pragma unroll
                for (int kc2 = 0; kc2 < 2; ++kc2) {
                    aa[kc2][0] = __ldcs(&ebA[grp + kc2 * 8 + i]);
                    aa[kc2][1] = __ldcs(&ebB[grp + kc2 * 8 + i]);
                    aa[kc2][2] = __ldcs(&ebA[grp + kc2 * 8 + 4 + i]);
                    aa[kc2][3] = __ldcs(&ebB[grp + kc2 * 8 + 4 + i]);
                }

                // normalized fp32 attn write
                if (arowA) {
                    int colbase = kt * 128 + sub * 64 + jq * 32 + 2 * i;
                    #pragma unroll
                    for (int kc2 = 0; kc2 < 2; ++kc2) {
                        float2 f0 = unpack_h2(aa[kc2][0]);
                        float2 f1 = unpack_h2(aa[kc2][1]);
                        float2 f2 = unpack_h2(aa[kc2][2]);
                        float2 f3 = unpack_h2(aa[kc2][3]);
                        __stcs((float2*)&arowA[colbase + kc2 * 16],
                               make_float2(f0.x * inva, f0.y * inva));
                        __stcs((float2*)&arowB[colbase + kc2 * 16],
                               make_float2(f1.x * invb, f1.y * invb));
                        __stcs((float2*)&arowA[colbase + kc2 * 16 + 8],
                               make_float2(f2.x * inva, f2.y * inva));
                        __stcs((float2*)&arowB[colbase + kc2 * 16 + 8],
                               make_float2(f3.x * invb, f3.y * invb));
                    }
                }

                // e @ V (2 products: e x Vhi + e x Vlo)
                #pragma unroll
                for (int dblk = 0; dblk < 8; ++dblk) {
                    u32 rb = (u32)(((dblk * 8 + trow) * VT_STR
                                    + sub * 32 + jq * 16 + tmat * 4) * 4);
                    u32 vh[4], vl[4];
                    ldm4(vh, vthi_u + rb);
                    ldm4(vl, vtlo_u + rb);
                    #pragma unroll
                    for (int kc2 = 0; kc2 < 2; ++kc2) {
                        mma16816(o[dblk], aa[kc2], vh[2 * kc2], vh[2 * kc2 + 1]);
                        mma16816(o[dblk], aa[kc2], vl[2 * kc2], vl[2 * kc2 + 1]);
                    }
                }
            }
        }

        if (kt + 1 < NKT) {
            const int nsel = ((kt + 1) & 1) * 2 * VBUF;
            stage_vt(Vb + (size_t)(kt + 1) * 128 * D_,
                     (u32*)(sm + nsel), (u32*)(sm + nsel + VBUF), tid);
        }
        __syncthreads();
    }

    if (outp) {
        float* orowA = outp + ((size_t)bh * S_ + q0 + qw + g) * D_ + 2 * i;
        float* orowB = orowA + 8 * D_;
        #pragma unroll
        for (int dblk = 0; dblk < 8; ++dblk) {
            *(float2*)&orowA[dblk * 8] = make_float2(o[dblk][0] * inva, o[dblk][1] * inva);
            *(float2*)&orowB[dblk * 8] = make_float2(o[dblk][2] * invb, o[dblk][3] * invb);
        }
    }
}

extern "C" void kernel_launch(void* const* d_in, const int* in_sizes, int n_in,
                              void* d_out, int out_size)
{
    const float* Q    = (const float*)d_in[0];
    const float* K    = (const float*)d_in[1];
    const float* V    = (const float*)d_in[2];
    const int*   mask = (const int*)d_in[3];

    const size_t OUT_E  = (size_t)B_ * H_ * S_ * D_;
    const size_t ATTN_E = (size_t)B_ * H_ * S_ * S_;
    float* o = nullptr; float* a = nullptr;
    if ((size_t)out_size >= OUT_E + ATTN_E) { o = (float*)d_out; a = (float*)d_out + OUT_E; }
    else if ((size_t)out_size == ATTN_E)    { a = (float*)d_out; }
    else                                    { o = (float*)d_out; }

    maskbits_kernel<<<(B_ * S_ * (S_ / 32)) / 256, 256>>>(mask);

    cudaFuncSetAttribute(attn_qk, cudaFuncAttributeMaxDynamicSharedMemorySize, SMEM_K);
    cudaFuncSetAttribute(attn_pv, cudaFuncAttributeMaxDynamicSharedMemorySize, SMEM_V);

    dim3 grid(S_ / 128, B_ * H_);
    attn_qk<<<grid, THREADS, SMEM_K>>>(Q, K);
    attn_pv<<<grid, THREADS, SMEM_V>>>(V, o, a);
}

// round 11
// speedup vs baseline: 1.8740x; 1.0581x over previous
#include <cuda_runtime.h>
#include <cuda_fp16.h>

typedef unsigned int u32;

#define B_ 4
#define H_ 16
#define S_ 2048
#define D_ 64
#define NKT 16
#define THREADS 256
#define KQ_STR 36      // u32 per K smem row (144B stride; conflict-free ldmatrix)
#define VT_STR 68      // u32 per Vt smem row (272B stride; conflict-free ldmatrix)

__device__ u32   g_mbits[(size_t)B_ * S_ * (S_ / 32)];     // 2 MB mask bitfield
__device__ float g_inv[(size_t)B_ * H_ * S_];              // per-row 1/sum
__device__ u32   g_ebuf[(size_t)B_ * H_ * S_ * (S_ / 2)];  // 0.54 GB fp16x2 e-buffer
// pre-converted operands, tile-major
__device__ u32   g_khi[(size_t)B_ * H_ * S_ * 32];         // [bh][s][32 u32]
__device__ u32   g_klo[(size_t)B_ * H_ * S_ * 32];
__device__ u32   g_vthi[(size_t)B_ * H_ * NKT * 4096];     // [bh][kt][64 d][64 kp]
__device__ u32   g_vtlo[(size_t)B_ * H_ * NKT * 4096];

// kernel1 smem: double-buffered K tiles (hi|lo per buffer)
#define KBUF   (128 * KQ_STR * 4)
#define SMEM_K (4 * KBUF)                                  // 73728 B -> 2 CTAs/SM
// kernel2 smem: double-buffered Vt tiles
#define VBUF   (64 * VT_STR * 4)
#define SMEM_V (4 * VBUF)                                  // 69632 B -> 2 CTAs/SM

__device__ __forceinline__ void mma16816(float c[4], const u32 a[4], u32 b0, u32 b1) {
    asm volatile("mma.sync.aligned.m16n8k16.row.col.f32.f16.f16.f32 "
                 "{%0,%1,%2,%3}, {%4,%5,%6,%7}, {%8,%9}, {%0,%1,%2,%3};"
                 : "+f"(c[0]), "+f"(c[1]), "+f"(c[2]), "+f"(c[3])
                 : "r"(a[0]), "r"(a[1]), "r"(a[2]), "r"(a[3]), "r"(b0), "r"(b1));
}

__device__ __forceinline__ void ldm4(u32* r, u32 addr) {
    asm volatile("ldmatrix.sync.aligned.m8n8.x4.shared.b16 {%0,%1,%2,%3}, [%4];"
                 : "=r"(r[0]), "=r"(r[1]), "=r"(r[2]), "=r"(r[3]) : "r"(addr));
}

__device__ __forceinline__ u32 smem_u32(const void* p) {
    return (u32)__cvta_generic_to_shared(p);
}

__device__ __forceinline__ void cpa16(u32 dst, const void* src) {
    asm volatile("cp.async.cg.shared.global [%0], [%1], 16;" :: "r"(dst), "l"(src));
}
#define CP_COMMIT() asm volatile("cp.async.commit_group;" ::: "memory")
#define CP_WAIT1()  asm volatile("cp.async.wait_group 1;" ::: "memory")
#define CP_WAIT0()  asm volatile("cp.async.wait_group 0;" ::: "memory")

// f32x2 -> packed f16x2 hi + residual lo
__device__ __forceinline__ void split2(float x, float y, u32& h, u32& l) {
    __half2 H = __floats2half2_rn(x, y);
    h = *reinterpret_cast<u32*>(&H);
    float2 f = __half22float2(H);
    __half2 L = __floats2half2_rn(x - f.x, y - f.y);
    l = *reinterpret_cast<u32*>(&L);
}
__device__ __forceinline__ u32 pack_h2(float x, float y) {
    __half2 H = __floats2half2_rn(x, y);
    return *reinterpret_cast<u32*>(&H);
}
__device__ __forceinline__ float2 unpack_h2(u32 v) {
    return __half22float2(*reinterpret_cast<__half2*>(&v));
}

__global__ void maskbits_kernel(const int* __restrict__ mask) {
    int w = blockIdx.x * blockDim.x + threadIdx.x;
    const int4* src = (const int4*)mask + (size_t)w * 8;
    u32 bits = 0;
    #pragma unroll
    for (int i = 0; i < 8; ++i) {
        int4 v = src[i];
        bits |= (v.x != 0 ? 1u : 0u) << (i * 4);
        bits |= (v.y != 0 ? 1u : 0u) << (i * 4 + 1);
        bits |= (v.z != 0 ? 1u : 0u) << (i * 4 + 2);
        bits |= (v.w != 0 ? 1u : 0u) << (i * 4 + 3);
    }
    g_mbits[w] = bits;
}

// ---- pre-convert K: fp32 [bh][s][64] -> hi/lo u32 planes [bh][s][32] ----
__global__ void conv_k(const float* __restrict__ K) {
    size_t idx = (size_t)blockIdx.x * blockDim.x + threadIdx.x;  // float4 index
    float4 v = ((const float4*)K)[idx];
    u32 h0, l0, h1, l1;
    split2(v.x, v.y, h0, l0);
    split2(v.z, v.w, h1, l1);
    ((uint2*)g_khi)[idx] = make_uint2(h0, h1);
    ((uint2*)g_klo)[idx] = make_uint2(l0, l1);
}

// ---- pre-convert + transpose V: fp32 [bh][k][64] -> Vt planes [bh][kt][64][64] ----
__global__ void conv_v(const float* __restrict__ V) {
    __shared__ u32 hi[64 * 64], lo[64 * 64];
    const int kt = blockIdx.x, bh = blockIdx.y, tid = threadIdx.x;
    const float4* s4 = (const float4*)(V + ((size_t)bh * S_ + kt * 128) * D_);
    #pragma unroll
    for (int it = 0; it < 4; ++it) {
        int idx = it * THREADS + tid;
        int d4 = idx & 15, kp = idx >> 4;
        float4 a = s4[(2 * kp) * 16 + d4];
        float4 b = s4[(2 * kp + 1) * 16 + d4];
        float av[4] = {a.x, a.y, a.z, a.w};
        float bv[4] = {b.x, b.y, b.z, b.w};
        #pragma unroll
        for (int dd0 = 0; dd0 < 4; ++dd0) {
            int dd = (dd0 + d4) & 3;
            u32 h, l;
            split2(av[dd], bv[dd], h, l);
            hi[(4 * d4 + dd) * 64 + kp] = h;
            lo[(4 * d4 + dd) * 64 + kp] = l;
        }
    }
    __syncthreads();
    const size_t base = ((size_t)bh * NKT + kt) * 4096;
    uint4* gh = (uint4*)(g_vthi + base);
    uint4* gl = (uint4*)(g_vtlo + base);
    #pragma unroll
    for (int it = 0; it < 4; ++it) {
        int idx = it * THREADS + tid;           // 0..1023 uint4
        gh[idx] = ((uint4*)hi)[idx];
        gl[idx] = ((uint4*)lo)[idx];
    }
}

// ---- cp.async staging into padded smem ----
__device__ __forceinline__ void stage_k_async(const u32* __restrict__ ghi,
                                              const u32* __restrict__ glo,
                                              u32 smhi, u32 smlo, int tid) {
    #pragma unroll
    for (int it = 0; it < 4; ++it) {
        int idx = it * THREADS + tid;           // 0..1023 16B chunks per plane
        int r = idx >> 3, c = idx & 7;
        u32 off = (u32)((r * KQ_STR + c * 4) * 4);
        cpa16(smhi + off, ghi + (size_t)idx * 4);
        cpa16(smlo + off, glo + (size_t)idx * 4);
    }
}
__device__ __forceinline__ void stage_v_async(const u32* __restrict__ ghi,
                                              const u32* __restrict__ glo,
                                              u32 smhi, u32 smlo, int tid) {
    #pragma unroll
    for (int it = 0; it < 4; ++it) {
        int idx = it * THREADS + tid;           // 0..1023 16B chunks per plane
        int r = idx >> 4, c = idx & 15;
        u32 off = (u32)((r * VT_STR + c * 4) * 4);
        cpa16(smhi + off, ghi + (size_t)idx * 4);
        cpa16(smlo + off, glo + (size_t)idx * 4);
    }
}

// ============ kernel 1: S=QK^T -> e=exp(masked) -> fp16 e-buffer + row sums ============
__global__ __launch_bounds__(THREADS, 2)
void attn_qk(const float* __restrict__ Q)
{
    extern __shared__ char sm[];

    const int tid = threadIdx.x, wid = tid >> 5, lane = tid & 31;
    const int g = lane >> 2, i = lane & 3;
    const int trow = lane & 7, tmat = lane >> 3;
    const int q0 = blockIdx.x * 128, bh = blockIdx.y, b = bh >> 4;
    const int qw = wid * 16;

    const u32* KbH = g_khi + (size_t)bh * S_ * 32;
    const u32* KbL = g_klo + (size_t)bh * S_ * 32;

    u32 qh[4][4], ql[4][4];
    {
        const float* qa = Q + ((size_t)bh * S_ + q0 + qw + g) * D_;
        const float* qb = qa + 8 * D_;
        #pragma unroll
        for (int kc = 0; kc < 4; ++kc) {
            float2 a0 = *(const float2*)(qa + 16 * kc + 2 * i);
            float2 a1 = *(const float2*)(qa + 16 * kc + 8 + 2 * i);
            float2 b0 = *(const float2*)(qb + 16 * kc + 2 * i);
            float2 b1 = *(const float2*)(qb + 16 * kc + 8 + 2 * i);
            split2(a0.x * 0.125f, a0.y * 0.125f, qh[kc][0], ql[kc][0]);
            split2(b0.x * 0.125f, b0.y * 0.125f, qh[kc][1], ql[kc][1]);
            split2(a1.x * 0.125f, a1.y * 0.125f, qh[kc][2], ql[kc][2]);
            split2(b1.x * 0.125f, b1.y * 0.125f, qh[kc][3], ql[kc][3]);
        }
    }

    const u32* mra = g_mbits + (size_t)(b * S_ + q0 + qw + g) * (S_ / 32);
    const u32* mrb = mra + 8 * (S_ / 32);
    u32* ebA = g_ebuf + (size_t)(bh * S_ + q0 + qw + g) * (S_ / 2);
    u32* ebB = ebA + 8 * (S_ / 2);

    float sa = 0.f, sb = 0.f;

    const u32 smbase = smem_u32(sm);
    // prologue: stage tile 0 into buffer 0
    stage_k_async(KbH, KbL, smbase, smbase + KBUF, tid);
    CP_COMMIT();

    for (int kt = 0; kt < NKT; ++kt) {
        if (kt + 1 < NKT) {
            const u32 nb = smbase + ((kt + 1) & 1) * 2 * KBUF;
            stage_k_async(KbH + (size_t)(kt + 1) * 128 * 32,
                          KbL + (size_t)(kt + 1) * 128 * 32, nb, nb + KBUF, tid);
            CP_COMMIT();
            CP_WAIT1();
        } else {
            CP_WAIT0();
        }
        __syncthreads();

        const u32 khi_u = smbase + (kt & 1) * 2 * KBUF;
        const u32 klo_u = khi_u + KBUF;

        #pragma unroll
        for (int sub = 0; sub < 2; ++sub) {
            #pragma unroll
            for (int jq = 0; jq < 2; ++jq) {
                float c[4][4];
                #pragma unroll
                for (int j = 0; j < 4; ++j)
                    c[j][0] = c[j][1] = c[j][2] = c[j][3] = 0.f;

                #pragma unroll
                for (int j4 = 0; j4 < 4; ++j4) {
                    int nrow = sub * 64 + jq * 32 + j4 * 8 + trow;
                    u32 rb = (u32)((nrow * KQ_STR + tmat * 4) * 4);
                    u32 bhv[8], blv[8];
                    ldm4(&bhv[0], khi_u + rb);
                    ldm4(&bhv[4], khi_u + rb + 64);
                    ldm4(&blv[0], klo_u + rb);
                    ldm4(&blv[4], klo_u + rb + 64);
                    #pragma unroll
                    for (int kc = 0; kc < 4; ++kc) {
                        mma16816(c[j4], qh[kc], bhv[2 * kc], bhv[2 * kc + 1]);
                        mma16816(c[j4], qh[kc], blv[2 * kc], blv[2 * kc + 1]);
                        mma16816(c[j4], ql[kc], bhv[2 * kc], bhv[2 * kc + 1]);
                    }
                }

                u32 wa = mra[kt * 4 + sub * 2 + jq];
                u32 wb = mrb[kt * 4 + sub * 2 + jq];
                int ubase = kt * 64 + sub * 32 + jq * 16 + i;
                #pragma unroll
                for (int j4 = 0; j4 < 4; ++j4) {
                    int sh = j4 * 8 + 2 * i;
                    u32 ba = wa >> sh, bb = wb >> sh;
                    float e0 = (ba & 1u) ? __expf(c[j4][0]) : 0.f;
                    float e1 = (ba & 2u) ? __expf(c[j4][1]) : 0.f;
                    float e2 = (bb & 1u) ? __expf(c[j4][2]) : 0.f;
                    float e3 = (bb & 2u) ? __expf(c[j4][3]) : 0.f;
                    sa += e0 + e1;
                    sb += e2 + e3;
                    __stcs(&ebA[ubase + j4 * 4], pack_h2(e0, e1));
                    __stcs(&ebB[ubase + j4 * 4], pack_h2(e2, e3));
                }
            }
        }
        __syncthreads();
    }

    sa += __shfl_xor_sync(0xffffffffu, sa, 1);
    sa += __shfl_xor_sync(0xffffffffu, sa, 2);
    sb += __shfl_xor_sync(0xffffffffu, sb, 1);
    sb += __shfl_xor_sync(0xffffffffu, sb, 2);
    if (i == 0) {
        g_inv[(size_t)bh * S_ + q0 + qw + g]     = (sa > 0.f) ? (1.0f / sa) : 0.f;
        g_inv[(size_t)bh * S_ + q0 + qw + g + 8] = (sb > 0.f) ? (1.0f / sb) : 0.f;
    }
}

// ============ kernel 2: attn = e*inv (fp32) + (e @ V)*inv -> out ============
__global__ __launch_bounds__(THREADS, 2)
void attn_pv(float* __restrict__ outp, float* __restrict__ attn)
{
    extern __shared__ char sm[];

    const int tid = threadIdx.x, wid = tid >> 5, lane = tid & 31;
    const int g = lane >> 2, i = lane & 3;
    const int trow = lane & 7, tmat = lane >> 3;
    const int q0 = blockIdx.x * 128, bh = blockIdx.y;
    const int qw = wid * 16;

    const u32* VbH = g_vthi + (size_t)bh * NKT * 4096;
    const u32* VbL = g_vtlo + (size_t)bh * NKT * 4096;
    const u32* ebA = g_ebuf + (size_t)(bh * S_ + q0 + qw + g) * (S_ / 2);
    const u32* ebB = ebA + 8 * (S_ / 2);

    float* arowA = nullptr; float* arowB = nullptr;
    if (attn) {
        arowA = attn + ((size_t)bh * S_ + q0 + qw + g) * S_;
        arowB = arowA + 8 * S_;
    }

    const float inva = __ldg(&g_inv[(size_t)bh * S_ + q0 + qw + g]);
    const float invb = __ldg(&g_inv[(size_t)bh * S_ + q0 + qw + g + 8]);

    float o[8][4];
    #pragma unroll
    for (int d = 0; d < 8; ++d) o[d][0] = o[d][1] = o[d][2] = o[d][3] = 0.f;

    const u32 smbase = smem_u32(sm);
    stage_v_async(VbH, VbL, smbase, smbase + VBUF, tid);
    CP_COMMIT();

    for (int kt = 0; kt < NKT; ++kt) {
        if (kt + 1 < NKT) {
            const u32 nb = smbase + ((kt + 1) & 1) * 2 * VBUF;
            stage_v_async(VbH + (size_t)(kt + 1) * 4096,
                          VbL + (size_t)(kt + 1) * 4096, nb, nb + VBUF, tid);
            CP_COMMIT();
            CP_WAIT1();
        } else {
            CP_WAIT0();
        }
        __syncthreads();

        const u32 vthi_u = smbase + (kt & 1) * 2 * VBUF;
        const u32 vtlo_u = vthi_u + VBUF;

        #pragma unroll
        for (int sub = 0; sub < 2; ++sub) {
            #pragma unroll
            for (int jq = 0; jq < 2; ++jq) {
                const int grp = kt * 64 + sub * 32 + jq * 16;

                u32 aa[2][4];
                #pragma unroll
                for (int kc2 = 0; kc2 < 2; ++kc2) {
                    aa[kc2][0] = __ldcs(&ebA[grp + kc2 * 8 + i]);
                    aa[kc2][1] = __ldcs(&ebB[grp + kc2 * 8 + i]);
                    aa[kc2][2] = __ldcs(&ebA[grp + kc2 * 8 + 4 + i]);
                    aa[kc2][3] = __ldcs(&ebB[grp + kc2 * 8 + 4 + i]);
                }

                if (arowA) {
                    int colbase = kt * 128 + sub * 64 + jq * 32 + 2 * i;
                    #pragma unroll
                    for (int kc2 = 0; kc2 < 2; ++kc2) {
                        float2 f0 = unpack_h2(aa[kc2][0]);
                        float2 f1 = unpack_h2(aa[kc2][1]);
                        float2 f2 = unpack_h2(aa[kc2][2]);
                        float2 f3 = unpack_h2(aa[kc2][3]);
                        __stcs((float2*)&arowA[colbase + kc2 * 16],
                               make_float2(f0.x * inva, f0.y * inva));
                        __stcs((float2*)&arowB[colbase + kc2 * 16],
                               make_float2(f1.x * invb, f1.y * invb));
                        __stcs((float2*)&arowA[colbase + kc2 * 16 + 8],
                               make_float2(f2.x * inva, f2.y * inva));
                        __stcs((float2*)&arowB[colbase + kc2 * 16 + 8],
                               make_float2(f3.x * invb, f3.y * invb));
                    }
                }

                #pragma unroll
                for (int dblk = 0; dblk < 8; ++dblk) {
                    u32 rb = (u32)(((dblk * 8 + trow) * VT_STR
                                    + sub * 32 + jq * 16 + tmat * 4) * 4);
                    u32 vh[4], vl[4];
                    ldm4(vh, vthi_u + rb);
                    ldm4(vl, vtlo_u + rb);
                    #pragma unroll
                    for (int kc2 = 0; kc2 < 2; ++kc2) {
                        mma16816(o[dblk], aa[kc2], vh[2 * kc2], vh[2 * kc2 + 1]);
                        mma16816(o[dblk], aa[kc2], vl[2 * kc2], vl[2 * kc2 + 1]);
                    }
                }
            }
        }
        __syncthreads();
    }

    if (outp) {
        float* orowA = outp + ((size_t)bh * S_ + q0 + qw + g) * D_ + 2 * i;
        float* orowB = orowA + 8 * D_;
        #pragma unroll
        for (int dblk = 0; dblk < 8; ++dblk) {
            *(float2*)&orowA[dblk * 8] = make_float2(o[dblk][0] * inva, o[dblk][1] * inva);
            *(float2*)&orowB[dblk * 8] = make_float2(o[dblk][2] * invb, o[dblk][3] * invb);
        }
    }
}

extern "C" void kernel_launch(void* const* d_in, const int* in_sizes, int n_in,
                              void* d_out, int out_size)
{
    const float* Q    = (const float*)d_in[0];
    const float* K    = (const float*)d_in[1];
    const float* V    = (const float*)d_in[2];
    const int*   mask = (const int*)d_in[3];

    const size_t OUT_E  = (size_t)B_ * H_ * S_ * D_;
    const size_t ATTN_E = (size_t)B_ * H_ * S_ * S_;
    float* o = nullptr; float* a = nullptr;
    if ((size_t)out_size >= OUT_E + ATTN_E) { o = (float*)d_out; a = (float*)d_out + OUT_E; }
    else if ((size_t)out_size == ATTN_E)    { a = (float*)d_out; }
    else                                    { o = (float*)d_out; }

    maskbits_kernel<<<(B_ * S_ * (S_ / 32)) / 256, 256>>>(mask);
    conv_k<<<(B_ * H_ * S_ * (D_ / 4)) / 256, 256>>>(K);
    conv_v<<<dim3(NKT, B_ * H_), 256>>>(V);

    cudaFuncSetAttribute(attn_qk, cudaFuncAttributeMaxDynamicSharedMemorySize, SMEM_K);
    cudaFuncSetAttribute(attn_pv, cudaFuncAttributeMaxDynamicSharedMemorySize, SMEM_V);

    dim3 grid(S_ / 128, B_ * H_);
    attn_qk<<<grid, THREADS, SMEM_K>>>(Q);
    attn_pv<<<grid, THREADS, SMEM_V>>>(o, a);
}